// round 3
// baseline (speedup 1.0000x reference)
#include <cuda_runtime.h>
#include <math.h>
#include <stdint.h>
#include <stddef.h>

// Problem constants
#define Bsz 64
#define Tt  100
#define Ss  400
#define Ee  512
#define Hh  1024
#define Kk  512
#define Vv  34

// ---------------- device scratch (static, no allocation) ----------------
__device__ float g_xs[(size_t)Tt * Bsz * Ee];   // [T][B][E] embedded inputs
__device__ float g_h1[2][Bsz * Hh];
__device__ float g_h2[2][Bsz * Hh];
__device__ float g_h3[2][Bsz * Hh];
__device__ float g_c1[Bsz * Hh];
__device__ float g_c2[Bsz * Hh];
__device__ float g_c3[Bsz * Hh];
__device__ float g_ctx[Bsz * Kk];
__device__ float g_q[Bsz * Kk];

// ---------------- embedding gather: xs[t][b][:] = emb[labels[b][t]] ----------------
__global__ void embed_kernel(const int* __restrict__ labels,
                             const float* __restrict__ emb) {
    int tb = blockIdx.x;          // over T*B
    int t = tb / Bsz;
    int b = tb % Bsz;
    int lab = labels[b * Tt + t];
    const float4* src = (const float4*)(emb + (size_t)lab * Ee);
    float4* dst = (float4*)(g_xs + ((size_t)t * Bsz + b) * Ee);
    for (int i = threadIdx.x; i < Ee / 4; i += blockDim.x) dst[i] = src[i];
}

// ---------------- init h/c buffers from h0 ----------------
__global__ void init_state_kernel(const float* __restrict__ h0) {
    int i = blockIdx.x * blockDim.x + threadIdx.x;
    if (i < Bsz * Hh) {
        float v = h0[i % Hh];
        g_h1[0][i] = v; g_h2[0][i] = v; g_h3[0][i] = v;
        g_c1[i] = v;    g_c2[i] = v;    g_c3[i] = v;
    }
}

// ---------------- init ctx0[b][k] = dot(h0, w_proj[k]) + b_proj[k] ----------------
__global__ void init_ctx_kernel(const float* __restrict__ h0,
                                const float* __restrict__ w_proj,
                                const float* __restrict__ b_proj) {
    int k = blockIdx.x;           // 0..K-1
    __shared__ float red[256];
    float s = 0.f;
    for (int i = threadIdx.x; i < Hh; i += 256)
        s += h0[i] * w_proj[(size_t)k * Hh + i];
    red[threadIdx.x] = s;
    __syncthreads();
    for (int off = 128; off; off >>= 1) {
        if (threadIdx.x < off) red[threadIdx.x] += red[threadIdx.x + off];
        __syncthreads();
    }
    float v = red[0] + b_proj[k];
    if (threadIdx.x < Bsz) g_ctx[(size_t)threadIdx.x * Kk + k] = v;
}

// ---------------- fused LSTM cell: gates GEMM + elementwise update ----------------
// Block: 8 hidden units (j0..j0+7) x 4 gates x all 64 batch rows.
// Grid: 128 blocks (H/8). 128 threads. Thread: 4 batch rows x 1 j x 4 gates.
__global__ void __launch_bounds__(128) lstm_kernel(
    int t, int cell,
    const float* __restrict__ w_ih, const float* __restrict__ w_hh,
    const float* __restrict__ b_ih, const float* __restrict__ b_hh)
{
    const int p = t & 1;
    const float* xa; const float* xb; int sa, sb, Da;
    const float* h_in; float* h_out; float* c;
    if (cell == 0) {
        xa = g_xs + (size_t)t * Bsz * Ee; sa = Ee;
        xb = g_ctx; sb = Kk; Da = Ee;
        h_in = g_h1[p]; h_out = g_h1[1 - p]; c = g_c1;
    } else if (cell == 1) {
        xa = g_h1[1 - p]; sa = Hh; xb = nullptr; sb = 0; Da = Hh;
        h_in = g_h2[p]; h_out = g_h2[1 - p]; c = g_c2;
    } else {
        xa = g_h2[1 - p]; sa = Hh; xb = nullptr; sb = 0; Da = Hh;
        h_in = g_h3[p]; h_out = g_h3[1 - p]; c = g_c3;
    }

    const int tid = threadIdx.x;
    const int jj  = tid & 7;      // 0..7   : hidden unit within block
    const int mg  = tid >> 3;     // 0..15  : group of 4 batch rows
    const int j0  = blockIdx.x * 8;
    const int kk4 = (tid & 7) * 4;
    const int ridx = tid >> 3;

    __shared__ float As[32][68];  // [k][m]   (padded)
    __shared__ float Ws[32][36];  // [k][jj*4+g]

    float acc[4][4];              // [mi][gate]
#pragma unroll
    for (int i = 0; i < 4; i++)
#pragma unroll
        for (int g = 0; g < 4; g++) acc[i][g] = 0.f;

    for (int phase = 0; phase < 2; phase++) {
        const float* __restrict__ W = phase ? w_hh : w_ih;
        for (int k0 = 0; k0 < 1024; k0 += 32) {
            // load A tile (64 rows x 32 k), transposed into smem
            const float* Ab; int kc, st;
            if (phase)          { Ab = h_in; kc = k0;       st = Hh; }
            else if (k0 < Da)   { Ab = xa;   kc = k0;       st = sa; }
            else                { Ab = xb;   kc = k0 - Da;  st = sb; }
#pragma unroll
            for (int rep = 0; rep < 4; rep++) {
                int m = rep * 16 + ridx;
                float4 v = *(const float4*)(Ab + (size_t)m * st + kc + kk4);
                As[kk4 + 0][m] = v.x; As[kk4 + 1][m] = v.y;
                As[kk4 + 2][m] = v.z; As[kk4 + 3][m] = v.w;
            }
            // load W tile (32 gate-rows x 32 k), transposed into smem
#pragma unroll
            for (int rep = 0; rep < 2; rep++) {
                int r = rep * 16 + ridx;                 // r = jjr*4 + g
                int grow = (r & 3) * Hh + j0 + (r >> 2); // gate chunk * H + j
                float4 v = *(const float4*)(W + (size_t)grow * 1024 + k0 + kk4);
                Ws[kk4 + 0][r] = v.x; Ws[kk4 + 1][r] = v.y;
                Ws[kk4 + 2][r] = v.z; Ws[kk4 + 3][r] = v.w;
            }
            __syncthreads();
#pragma unroll
            for (int kk = 0; kk < 32; kk++) {
                float4 a4 = *(const float4*)&As[kk][mg * 4];
                float4 w4 = *(const float4*)&Ws[kk][jj * 4];
                acc[0][0] += a4.x * w4.x; acc[0][1] += a4.x * w4.y;
                acc[0][2] += a4.x * w4.z; acc[0][3] += a4.x * w4.w;
                acc[1][0] += a4.y * w4.x; acc[1][1] += a4.y * w4.y;
                acc[1][2] += a4.y * w4.z; acc[1][3] += a4.y * w4.w;
                acc[2][0] += a4.z * w4.x; acc[2][1] += a4.z * w4.y;
                acc[2][2] += a4.z * w4.z; acc[2][3] += a4.z * w4.w;
                acc[3][0] += a4.w * w4.x; acc[3][1] += a4.w * w4.y;
                acc[3][2] += a4.w * w4.z; acc[3][3] += a4.w * w4.w;
            }
            __syncthreads();
        }
    }

    // elementwise LSTM update (gate order: i, f, g, o)
    const int jg = j0 + jj;
    const float bs0 = b_ih[0 * Hh + jg] + b_hh[0 * Hh + jg];
    const float bs1 = b_ih[1 * Hh + jg] + b_hh[1 * Hh + jg];
    const float bs2 = b_ih[2 * Hh + jg] + b_hh[2 * Hh + jg];
    const float bs3 = b_ih[3 * Hh + jg] + b_hh[3 * Hh + jg];
#pragma unroll
    for (int mi = 0; mi < 4; mi++) {
        int m = mg * 4 + mi;
        float ig = acc[mi][0] + bs0;
        float fg = acc[mi][1] + bs1;
        float gg = acc[mi][2] + bs2;
        float og = acc[mi][3] + bs3;
        float si = 1.f / (1.f + expf(-ig));
        float sf = 1.f / (1.f + expf(-fg));
        float so = 1.f / (1.f + expf(-og));
        float tg = tanhf(gg);
        float cn = sf * c[(size_t)m * Hh + jg] + si * tg;
        c[(size_t)m * Hh + jg] = cn;
        h_out[(size_t)m * Hh + jg] = so * tanhf(cn);
    }
}

// ---------------- q = h3 @ w_proj^T + b_proj ----------------
__global__ void proj_q_kernel(int t,
                              const float* __restrict__ w_proj,
                              const float* __restrict__ b_proj) {
    const float* h3 = g_h3[1 - (t & 1)];
    int idx = blockIdx.x * blockDim.x + threadIdx.x;  // over B*K
    if (idx >= Bsz * Kk) return;
    int b = idx >> 9;     // / 512
    int k = idx & 511;
    const float4* hr = (const float4*)(h3 + (size_t)b * Hh);
    const float4* wr = (const float4*)(w_proj + (size_t)k * Hh);
    float a0 = 0.f, a1 = 0.f, a2 = 0.f, a3 = 0.f;
#pragma unroll 4
    for (int i = 0; i < Hh / 4; i += 4) {
        float4 h4, w4;
        h4 = hr[i + 0]; w4 = wr[i + 0];
        a0 += h4.x * w4.x + h4.y * w4.y + h4.z * w4.z + h4.w * w4.w;
        h4 = hr[i + 1]; w4 = wr[i + 1];
        a1 += h4.x * w4.x + h4.y * w4.y + h4.z * w4.z + h4.w * w4.w;
        h4 = hr[i + 2]; w4 = wr[i + 2];
        a2 += h4.x * w4.x + h4.y * w4.y + h4.z * w4.z + h4.w * w4.w;
        h4 = hr[i + 3]; w4 = wr[i + 3];
        a3 += h4.x * w4.x + h4.y * w4.y + h4.z * w4.z + h4.w * w4.w;
    }
    g_q[idx] = (a0 + a1) + (a2 + a3) + b_proj[k];
}

// ---------------- fused attention: energy, softmax, ctx, score ----------------
// Grid: B blocks, 512 threads.
__global__ void __launch_bounds__(512) attn_kernel(
    int t,
    const float* __restrict__ keys,     // [S][B][K]
    const float* __restrict__ values,   // [S][B][K]
    const float* __restrict__ w_score,  // [V][2K]
    const float* __restrict__ b_score,  // [V]
    float* __restrict__ out_pred,       // [B][T][V]
    float* __restrict__ out_attn)       // [B][T][S]
{
    const int b = blockIdx.x;
    const int tid = threadIdx.x;
    const int lane = tid & 31;
    const int wid  = tid >> 5;          // 16 warps

    __shared__ float sq[Kk];
    __shared__ float sattn[Ss];
    __shared__ float sctx[Kk];
    __shared__ float red[16];

    for (int i = tid; i < Kk; i += 512) sq[i] = g_q[(size_t)b * Kk + i];
    __syncthreads();

    // energy: warp per s (coalesced key reads)
    for (int s = wid; s < Ss; s += 16) {
        const float4* kr = (const float4*)(keys + ((size_t)s * Bsz + b) * Kk);
        const float4* qr = (const float4*)sq;
        float acc = 0.f;
#pragma unroll
        for (int i = 0; i < 4; i++) {
            float4 k4 = kr[i * 32 + lane];
            float4 q4 = qr[i * 32 + lane];
            acc += k4.x * q4.x + k4.y * q4.y + k4.z * q4.z + k4.w * q4.w;
        }
        for (int off = 16; off; off >>= 1)
            acc += __shfl_xor_sync(0xffffffffu, acc, off);
        if (lane == 0) sattn[s] = acc;
    }
    __syncthreads();

    // softmax over S
    float m = -3.4e38f;
    for (int s = tid; s < Ss; s += 512) m = fmaxf(m, sattn[s]);
    for (int off = 16; off; off >>= 1)
        m = fmaxf(m, __shfl_xor_sync(0xffffffffu, m, off));
    if (lane == 0) red[wid] = m;
    __syncthreads();
    if (wid == 0) {
        float v = (lane < 16) ? red[lane] : -3.4e38f;
        for (int off = 8; off; off >>= 1)
            v = fmaxf(v, __shfl_xor_sync(0xffffffffu, v, off));
        if (lane == 0) red[0] = v;
    }
    __syncthreads();
    const float mx = red[0];
    __syncthreads();

    float sum = 0.f;
    for (int s = tid; s < Ss; s += 512) {
        float e = expf(sattn[s] - mx);
        sattn[s] = e;
        sum += e;
    }
    for (int off = 16; off; off >>= 1)
        sum += __shfl_xor_sync(0xffffffffu, sum, off);
    if (lane == 0) red[wid] = sum;
    __syncthreads();
    if (wid == 0) {
        float v = (lane < 16) ? red[lane] : 0.f;
        for (int off = 8; off; off >>= 1)
            v += __shfl_xor_sync(0xffffffffu, v, off);
        if (lane == 0) red[0] = v;
    }
    __syncthreads();
    const float inv = 1.f / red[0];
    for (int s = tid; s < Ss; s += 512) {
        float a = sattn[s] * inv;
        sattn[s] = a;
        out_attn[((size_t)b * Tt + t) * Ss + s] = a;
    }
    __syncthreads();

    // ctx[k] = sum_s attn[s] * values[s][b][k]  (thread per k; coalesced)
    {
        float a0 = 0.f, a1 = 0.f;
        const size_t base = (size_t)b * Kk + tid;
        const size_t stride = (size_t)Bsz * Kk;
        for (int s = 0; s < Ss; s += 2) {
            a0 += sattn[s]     * values[base + (size_t)s * stride];
            a1 += sattn[s + 1] * values[base + (size_t)(s + 1) * stride];
        }
        float accv = a0 + a1;
        sctx[tid] = accv;
        g_ctx[(size_t)b * Kk + tid] = accv;  // feeds next step's LSTM1
    }
    __syncthreads();

    // score[v] = dot(w_score[v], [q, ctx]) + b_score[v]  (warp per v)
    for (int v = wid; v < Vv; v += 16) {
        const float* wr = w_score + (size_t)v * (2 * Kk);
        float acc = 0.f;
        for (int i = lane; i < Kk; i += 32)
            acc += sq[i] * wr[i] + sctx[i] * wr[Kk + i];
        for (int off = 16; off; off >>= 1)
            acc += __shfl_xor_sync(0xffffffffu, acc, off);
        if (lane == 0)
            out_pred[((size_t)b * Tt + t) * Vv + v] = acc + b_score[v];
    }
}

// ---------------- launch ----------------
extern "C" void kernel_launch(void* const* d_in, const int* in_sizes, int n_in,
                              void* d_out, int out_size) {
    const int*   labels  = (const int*)  d_in[0];
    const float* keys    = (const float*)d_in[1];
    const float* values  = (const float*)d_in[2];
    const float* emb     = (const float*)d_in[3];
    const float* w_ih0   = (const float*)d_in[4];
    const float* w_hh0   = (const float*)d_in[5];
    const float* b_ih0   = (const float*)d_in[6];
    const float* b_hh0   = (const float*)d_in[7];
    const float* w_ih1   = (const float*)d_in[8];
    const float* w_hh1   = (const float*)d_in[9];
    const float* b_ih1   = (const float*)d_in[10];
    const float* b_hh1   = (const float*)d_in[11];
    const float* w_ih2   = (const float*)d_in[12];
    const float* w_hh2   = (const float*)d_in[13];
    const float* b_ih2   = (const float*)d_in[14];
    const float* b_hh2   = (const float*)d_in[15];
    const float* w_proj  = (const float*)d_in[16];
    const float* b_proj  = (const float*)d_in[17];
    const float* w_score = (const float*)d_in[18];
    const float* b_score = (const float*)d_in[19];
    const float* h0      = (const float*)d_in[20];

    float* out_pred = (float*)d_out;
    float* out_attn = out_pred + (size_t)Bsz * Tt * Vv;

    embed_kernel<<<Tt * Bsz, 128>>>(labels, emb);
    init_state_kernel<<<(Bsz * Hh + 255) / 256, 256>>>(h0);
    init_ctx_kernel<<<Kk, 256>>>(h0, w_proj, b_proj);

    for (int t = 0; t < Tt; t++) {
        lstm_kernel<<<128, 128>>>(t, 0, w_ih0, w_hh0, b_ih0, b_hh0);
        lstm_kernel<<<128, 128>>>(t, 1, w_ih1, w_hh1, b_ih1, b_hh1);
        lstm_kernel<<<128, 128>>>(t, 2, w_ih2, w_hh2, b_ih2, b_hh2);
        proj_q_kernel<<<(Bsz * Kk + 255) / 256, 256>>>(t, w_proj, b_proj);
        attn_kernel<<<Bsz, 512>>>(t, keys, values, w_score, b_score,
                                  out_pred, out_attn);
    }
}

// round 5
// speedup vs baseline: 2.2311x; 2.2311x over previous
#include <cuda_runtime.h>
#include <math.h>
#include <stdint.h>
#include <stddef.h>

#define Bsz 64
#define Tt  100
#define Ss  400
#define Ee  512
#define Hh  1024
#define Kk  512
#define Vv  34

// ---------------- static device scratch ----------------
__device__ __align__(256) float g_wcat[3][4096 * 2048];     // tf32 weights [cell][row][k0..2048)
__device__ __align__(256) float g_xs[(size_t)Tt * Bsz * Ee]; // tf32 embedded inputs
__device__ __align__(256) float g_h1t[2][Bsz * Hh];          // tf32 h states (ping-pong)
__device__ __align__(256) float g_h2t[2][Bsz * Hh];
__device__ __align__(256) float g_h3t[2][Bsz * Hh];
__device__ __align__(256) float g_h3f[2][Bsz * Hh];          // fp32 h3 (for proj)
__device__ __align__(256) float g_c1[Bsz * Hh];
__device__ __align__(256) float g_c2[Bsz * Hh];
__device__ __align__(256) float g_c3[Bsz * Hh];
__device__ __align__(256) float g_ctx[Bsz * Kk];             // fp32 (score)
__device__ __align__(256) float g_ctxt[Bsz * Kk];            // tf32 (gemm)
__device__ __align__(256) float g_q[Bsz * Kk];
__device__ __align__(256) float g_energy[Bsz * Ss];

// ---------------- helpers ----------------
__device__ __forceinline__ float to_tf32(float x) {
    uint32_t u;
    asm("cvt.rna.tf32.f32 %0, %1;" : "=r"(u) : "f"(x));
    return __uint_as_float(u);
}

__device__ __forceinline__ void cpa16(uint32_t dst, const void* src) {
    asm volatile("cp.async.ca.shared.global [%0], [%1], 16;\n" :: "r"(dst), "l"(src));
}
#define CPA_COMMIT() asm volatile("cp.async.commit_group;\n" ::: "memory")
#define CPA_WAIT(n)  asm volatile("cp.async.wait_group %0;\n" :: "n"(n) : "memory")

__device__ __forceinline__ void mma_tf32(float* c,
    uint32_t a0, uint32_t a1, uint32_t a2, uint32_t a3,
    uint32_t b0, uint32_t b1) {
    asm volatile(
        "mma.sync.aligned.m16n8k8.row.col.f32.tf32.tf32.f32 "
        "{%0,%1,%2,%3},{%4,%5,%6,%7},{%8,%9},{%0,%1,%2,%3};\n"
        : "+f"(c[0]), "+f"(c[1]), "+f"(c[2]), "+f"(c[3])
        : "r"(a0), "r"(a1), "r"(a2), "r"(a3), "r"(b0), "r"(b1));
}

// ---------------- weight conversion (fp32 -> tf32, concat ih|hh) ----------------
__global__ void convert_w_kernel(const float* __restrict__ w_ih,
                                 const float* __restrict__ w_hh,
                                 float* __restrict__ dst) {
    int r = blockIdx.x;                     // 0..4095
    int i = threadIdx.x;                    // 0..255, one float4 per half
    const float4* a = (const float4*)(w_ih + (size_t)r * 1024);
    const float4* b = (const float4*)(w_hh + (size_t)r * 1024);
    float4* d0 = (float4*)(dst + (size_t)r * 2048);
    float4 va = a[i];
    va.x = to_tf32(va.x); va.y = to_tf32(va.y);
    va.z = to_tf32(va.z); va.w = to_tf32(va.w);
    d0[i] = va;
    float4 vb = b[i];
    vb.x = to_tf32(vb.x); vb.y = to_tf32(vb.y);
    vb.z = to_tf32(vb.z); vb.w = to_tf32(vb.w);
    d0[256 + i] = vb;
}

// ---------------- embedding gather (stores tf32) ----------------
__global__ void embed_kernel(const int* __restrict__ labels,
                             const float* __restrict__ emb) {
    int tb = blockIdx.x;
    int t = tb / Bsz;
    int b = tb % Bsz;
    int lab = labels[b * Tt + t];
    const float4* src = (const float4*)(emb + (size_t)lab * Ee);
    float4* dst = (float4*)(g_xs + ((size_t)t * Bsz + b) * Ee);
    for (int i = threadIdx.x; i < Ee / 4; i += blockDim.x) {
        float4 v = src[i];
        v.x = to_tf32(v.x); v.y = to_tf32(v.y);
        v.z = to_tf32(v.z); v.w = to_tf32(v.w);
        dst[i] = v;
    }
}

// ---------------- init h/c ----------------
__global__ void init_state_kernel(const float* __restrict__ h0) {
    int i = blockIdx.x * blockDim.x + threadIdx.x;
    if (i < Bsz * Hh) {
        float v = h0[i % Hh];
        float vt = to_tf32(v);
        g_h1t[0][i] = vt; g_h2t[0][i] = vt; g_h3t[0][i] = vt;
        g_h3f[0][i] = v;
        g_c1[i] = v; g_c2[i] = v; g_c3[i] = v;
    }
}

// ---------------- init ctx0 ----------------
__global__ void init_ctx_kernel(const float* __restrict__ h0,
                                const float* __restrict__ w_proj,
                                const float* __restrict__ b_proj) {
    int k = blockIdx.x;
    __shared__ float red[256];
    float s = 0.f;
    for (int i = threadIdx.x; i < Hh; i += 256)
        s += h0[i] * w_proj[(size_t)k * Hh + i];
    red[threadIdx.x] = s;
    __syncthreads();
    for (int off = 128; off; off >>= 1) {
        if (threadIdx.x < off) red[threadIdx.x] += red[threadIdx.x + off];
        __syncthreads();
    }
    float v = red[0] + b_proj[k];
    if (threadIdx.x < Bsz) {
        g_ctx[(size_t)threadIdx.x * Kk + k]  = v;
        g_ctxt[(size_t)threadIdx.x * Kk + k] = to_tf32(v);
    }
}

// ---------------- tf32 MMA LSTM cell ----------------
// C[64 x 4096] = A[64 x 2048] @ Wcat^T ; block owns 8 j x 4 gates (N=32 cols),
// grid = 128 blocks, 256 threads (8 warps: 4 m-tiles x 2 n-halves).
#define BK 64
#define STAGES 3
#define A_PAD 68
#define B_PAD 68
#define A_ST (64 * A_PAD)
#define B_ST (32 * B_PAD)
#define STAGE_FLOATS (A_ST + B_ST)
#define LSTM_SMEM (STAGES * STAGE_FLOATS * 4)

struct SegInfo { const float* p; int stride; };

__device__ __forceinline__ SegInfo a_seg(int cell, int p, int t, int seg) {
    SegInfo r;
    if (cell == 0) {
        if (seg == 0)      { r.p = g_xs + (size_t)t * Bsz * Ee; r.stride = Ee; }
        else if (seg == 1) { r.p = g_ctxt;                      r.stride = Kk; }
        else               { r.p = g_h1t[p] + (seg - 2) * 512;  r.stride = Hh; }
    } else if (cell == 1) {
        if (seg < 2) { r.p = g_h1t[1 - p] + seg * 512;       r.stride = Hh; }
        else         { r.p = g_h2t[p]     + (seg - 2) * 512; r.stride = Hh; }
    } else {
        if (seg < 2) { r.p = g_h2t[1 - p] + seg * 512;       r.stride = Hh; }
        else         { r.p = g_h3t[p]     + (seg - 2) * 512; r.stride = Hh; }
    }
    return r;
}

__global__ void __launch_bounds__(256) lstm_mma_kernel(
    int cell, int t,
    const float* __restrict__ b_ih, const float* __restrict__ b_hh)
{
    extern __shared__ float smem[];
    const int p = t & 1;
    const int tid = threadIdx.x;
    const int lane = tid & 31;
    const int warp = tid >> 5;
    const int wm = warp & 3;
    const int wn = warp >> 2;
    const int j0 = blockIdx.x * 8;
    const float* __restrict__ wcat = g_wcat[cell];

    float* c_st; float* h_tf; float* h_f;
    if (cell == 0)      { c_st = g_c1; h_tf = g_h1t[1 - p]; h_f = nullptr; }
    else if (cell == 1) { c_st = g_c2; h_tf = g_h2t[1 - p]; h_f = nullptr; }
    else                { c_st = g_c3; h_tf = g_h3t[1 - p]; h_f = g_h3f[1 - p]; }

    const uint32_t smem_u = (uint32_t)__cvta_generic_to_shared(smem);

    float acc0[4] = {0.f, 0.f, 0.f, 0.f};
    float acc1[4] = {0.f, 0.f, 0.f, 0.f};

    const int NTILES = 2048 / BK;   // 32

    // ---- tile issue ----
    auto issue_tile = [&](int kt, int ss) {
        const int k0 = kt * BK;
        SegInfo si = a_seg(cell, p, t, k0 >> 9);
        const int kin = k0 & 511;
        const uint32_t abase = smem_u + (uint32_t)(ss * STAGE_FLOATS) * 4u;
        const uint32_t bbase = abase + (uint32_t)A_ST * 4u;
#pragma unroll
        for (int j = 0; j < 4; j++) {              // A: 1024 float4
            int i = tid + j * 256;
            int m = i >> 4, f4 = i & 15;
            const float* src = si.p + (size_t)m * si.stride + kin + f4 * 4;
            cpa16(abase + (uint32_t)(m * A_PAD + f4 * 4) * 4u, src);
        }
#pragma unroll
        for (int j = 0; j < 2; j++) {              // B: 512 float4
            int i = tid + j * 256;
            int n = i >> 4, f4 = i & 15;
            int r = (n >> 3) * 1024 + j0 + (n & 7);
            const float* src = wcat + (size_t)r * 2048 + k0 + f4 * 4;
            cpa16(bbase + (uint32_t)(n * B_PAD + f4 * 4) * 4u, src);
        }
    };

    // prologue: tiles 0,1
    issue_tile(0, 0); CPA_COMMIT();
    issue_tile(1, 1); CPA_COMMIT();

    const int ar = lane >> 2;   // 0..7
    const int ac = lane & 3;    // 0..3
    const int arow = wm * 16 + ar;

    for (int kt = 0; kt < NTILES; kt++) {
        if (kt + 2 < NTILES) issue_tile(kt + 2, (kt + 2) % STAGES);
        CPA_COMMIT();
        CPA_WAIT(2);
        __syncthreads();

        const float* As = smem + (kt % STAGES) * STAGE_FLOATS;
        const float* Bs = As + A_ST;
#pragma unroll
        for (int ks = 0; ks < BK / 8; ks++) {
            const int kb = ks * 8;
            uint32_t a0 = __float_as_uint(As[arow * A_PAD + kb + ac]);
            uint32_t a1 = __float_as_uint(As[(arow + 8) * A_PAD + kb + ac]);
            uint32_t a2 = __float_as_uint(As[arow * A_PAD + kb + ac + 4]);
            uint32_t a3 = __float_as_uint(As[(arow + 8) * A_PAD + kb + ac + 4]);
            {
                int n = wn * 16 + ar;
                uint32_t b0 = __float_as_uint(Bs[n * B_PAD + kb + ac]);
                uint32_t b1 = __float_as_uint(Bs[n * B_PAD + kb + ac + 4]);
                mma_tf32(acc0, a0, a1, a2, a3, b0, b1);
            }
            {
                int n = wn * 16 + 8 + ar;
                uint32_t b0 = __float_as_uint(Bs[n * B_PAD + kb + ac]);
                uint32_t b1 = __float_as_uint(Bs[n * B_PAD + kb + ac + 4]);
                mma_tf32(acc1, a0, a1, a2, a3, b0, b1);
            }
        }
        __syncthreads();
    }
    CPA_WAIT(0);

    // ---- stage C through smem: Cs[64][33], col n = g*8 + jj ----
    float* Cs = smem;
    {
        int crow = wm * 16 + ar;
        int cc0 = wn * 16 + 2 * ac;
        Cs[crow * 33 + cc0]           = acc0[0];
        Cs[crow * 33 + cc0 + 1]       = acc0[1];
        Cs[(crow + 8) * 33 + cc0]     = acc0[2];
        Cs[(crow + 8) * 33 + cc0 + 1] = acc0[3];
        Cs[crow * 33 + cc0 + 8]           = acc1[0];
        Cs[crow * 33 + cc0 + 9]           = acc1[1];
        Cs[(crow + 8) * 33 + cc0 + 8]     = acc1[2];
        Cs[(crow + 8) * 33 + cc0 + 9]     = acc1[3];
    }
    __syncthreads();

    // ---- fused LSTM update: 512 (m, jj) pairs, 2 per thread ----
#pragma unroll
    for (int j = 0; j < 2; j++) {
        int pr = tid + j * 256;
        int m = pr & 63;
        int jj = pr >> 6;
        int jg = j0 + jj;
        float gi = Cs[m * 33 + jj]      + b_ih[jg]          + b_hh[jg];
        float gf = Cs[m * 33 + 8 + jj]  + b_ih[1024 + jg]   + b_hh[1024 + jg];
        float gg = Cs[m * 33 + 16 + jj] + b_ih[2048 + jg]   + b_hh[2048 + jg];
        float go = Cs[m * 33 + 24 + jj] + b_ih[3072 + jg]   + b_hh[3072 + jg];
        float si = 1.f / (1.f + expf(-gi));
        float sf = 1.f / (1.f + expf(-gf));
        float so = 1.f / (1.f + expf(-go));
        float cn = sf * c_st[(size_t)m * Hh + jg] + si * tanhf(gg);
        c_st[(size_t)m * Hh + jg] = cn;
        float hn = so * tanhf(cn);
        h_tf[(size_t)m * Hh + jg] = to_tf32(hn);
        if (h_f) h_f[(size_t)m * Hh + jg] = hn;
    }
}

// ---------------- q = h3 @ w_proj^T + b_proj (smem-tiled) ----------------
// grid 64 blocks: block kb owns 8 k's; 256 threads.
__global__ void __launch_bounds__(256) proj_q_kernel(
    int t, const float* __restrict__ w_proj, const float* __restrict__ b_proj)
{
    __shared__ float sw[8 * 1024];
    const int tid = threadIdx.x;
    const int kb = blockIdx.x;
    const float4* wp4 = (const float4*)(w_proj + (size_t)kb * 8 * 1024);
    float4* sw4 = (float4*)sw;
#pragma unroll
    for (int j = 0; j < 8; j++) sw4[tid + j * 256] = wp4[tid + j * 256];
    __syncthreads();

    const float* h3 = g_h3f[1 - (t & 1)];
    int b = tid >> 2;
    int kl = tid & 3;
    const float4* hr = (const float4*)(h3 + (size_t)b * Hh);
    const float4* w0 = (const float4*)(sw + kl * 1024);
    const float4* w1 = (const float4*)(sw + (kl + 4) * 1024);
    float a0 = 0.f, a1 = 0.f;
#pragma unroll 4
    for (int i = 0; i < 256; i++) {
        float4 h4 = hr[i];
        float4 x0 = w0[i];
        float4 x1 = w1[i];
        a0 += h4.x * x0.x + h4.y * x0.y + h4.z * x0.z + h4.w * x0.w;
        a1 += h4.x * x1.x + h4.y * x1.y + h4.z * x1.z + h4.w * x1.w;
    }
    int kg = kb * 8 + kl;
    g_q[(size_t)b * Kk + kg]     = a0 + b_proj[kg];
    g_q[(size_t)b * Kk + kg + 4] = a1 + b_proj[kg + 4];
}

// ---------------- energy: grid (64 b, 8 s-chunks), 256 threads ----------------
__global__ void __launch_bounds__(256) energy_kernel(const float* __restrict__ keys) {
    const int b = blockIdx.x;
    const int sc = blockIdx.y;
    const int tid = threadIdx.x;
    const int lane = tid & 31;
    const int wid = tid >> 5;
    __shared__ float sq[Kk];
    if (tid < 128)
        ((float4*)sq)[tid] = ((const float4*)(g_q + (size_t)b * Kk))[tid];
    __syncthreads();
    const float4* qr = (const float4*)sq;
    for (int s = sc * 50 + wid; s < sc * 50 + 50; s += 8) {
        const float4* kr = (const float4*)(keys + ((size_t)s * Bsz + b) * Kk);
        float acc = 0.f;
#pragma unroll
        for (int i = 0; i < 4; i++) {
            float4 k4 = kr[lane + i * 32];
            float4 q4 = qr[lane + i * 32];
            acc += k4.x * q4.x + k4.y * q4.y + k4.z * q4.z + k4.w * q4.w;
        }
#pragma unroll
        for (int off = 16; off; off >>= 1)
            acc += __shfl_xor_sync(0xffffffffu, acc, off);
        if (lane == 0) g_energy[b * Ss + s] = acc;
    }
}

// ---------------- softmax: grid 64, 512 threads ----------------
__global__ void __launch_bounds__(512) softmax_kernel(int t, float* __restrict__ out_attn) {
    const int b = blockIdx.x;
    const int tid = threadIdx.x;
    const int lane = tid & 31;
    const int wid = tid >> 5;
    __shared__ float se[Ss];
    __shared__ float red[16];
    for (int s = tid; s < Ss; s += 512) se[s] = g_energy[b * Ss + s];
    __syncthreads();

    float m = -3.4e38f;
    for (int s = tid; s < Ss; s += 512) m = fmaxf(m, se[s]);
#pragma unroll
    for (int off = 16; off; off >>= 1)
        m = fmaxf(m, __shfl_xor_sync(0xffffffffu, m, off));
    if (lane == 0) red[wid] = m;
    __syncthreads();
    if (wid == 0) {
        float v = (lane < 16) ? red[lane] : -3.4e38f;
#pragma unroll
        for (int off = 8; off; off >>= 1)
            v = fmaxf(v, __shfl_xor_sync(0xffffffffu, v, off));
        if (lane == 0) red[0] = v;
    }
    __syncthreads();
    const float mx = red[0];
    __syncthreads();

    float sum = 0.f;
    for (int s = tid; s < Ss; s += 512) {
        float e = expf(se[s] - mx);
        se[s] = e;
        sum += e;
    }
#pragma unroll
    for (int off = 16; off; off >>= 1)
        sum += __shfl_xor_sync(0xffffffffu, sum, off);
    if (lane == 0) red[wid] = sum;
    __syncthreads();
    if (wid == 0) {
        float v = (lane < 16) ? red[lane] : 0.f;
#pragma unroll
        for (int off = 8; off; off >>= 1)
            v += __shfl_xor_sync(0xffffffffu, v, off);
        if (lane == 0) red[0] = v;
    }
    __syncthreads();
    const float inv = 1.f / red[0];
    for (int s = tid; s < Ss; s += 512)
        out_attn[((size_t)b * Tt + t) * Ss + s] = se[s] * inv;
}

// ---------------- ctx: grid (4 k-chunks, 64 b), 128 threads ----------------
__global__ void __launch_bounds__(128) ctx_kernel(
    int t, const float* __restrict__ values, const float* __restrict__ out_attn)
{
    const int kc = blockIdx.x;
    const int b = blockIdx.y;
    const int tid = threadIdx.x;
    __shared__ float sat[Ss];
    const float* ap = out_attn + ((size_t)b * Tt + t) * Ss;
    for (int i = tid; i < Ss; i += 128) sat[i] = ap[i];
    __syncthreads();

    const int k = kc * 128 + tid;
    const size_t base = (size_t)b * Kk + k;
    const size_t str = (size_t)Bsz * Kk;
    float a0 = 0.f, a1 = 0.f, a2 = 0.f, a3 = 0.f;
    for (int s = 0; s < Ss; s += 4) {
        a0 += sat[s]     * values[base + (size_t)s * str];
        a1 += sat[s + 1] * values[base + (size_t)(s + 1) * str];
        a2 += sat[s + 2] * values[base + (size_t)(s + 2) * str];
        a3 += sat[s + 3] * values[base + (size_t)(s + 3) * str];
    }
    float r = (a0 + a1) + (a2 + a3);
    g_ctx[(size_t)b * Kk + k]  = r;
    g_ctxt[(size_t)b * Kk + k] = to_tf32(r);
}

// ---------------- score: grid 64, 256 threads ----------------
__global__ void __launch_bounds__(256) score_kernel(
    int t, const float* __restrict__ w_score, const float* __restrict__ b_score,
    float* __restrict__ out_pred)
{
    const int b = blockIdx.x;
    const int tid = threadIdx.x;
    const int lane = tid & 31;
    const int wid = tid >> 5;
    __shared__ float sq[Kk];
    __shared__ float sc[Kk];
    for (int i = tid; i < Kk; i += 256) {
        sq[i] = g_q[(size_t)b * Kk + i];
        sc[i] = g_ctx[(size_t)b * Kk + i];
    }
    __syncthreads();
    for (int v = wid; v < Vv; v += 8) {
        const float* wr = w_score + (size_t)v * (2 * Kk);
        float acc = 0.f;
        for (int i = lane; i < Kk; i += 32)
            acc += sq[i] * wr[i] + sc[i] * wr[Kk + i];
#pragma unroll
        for (int off = 16; off; off >>= 1)
            acc += __shfl_xor_sync(0xffffffffu, acc, off);
        if (lane == 0)
            out_pred[((size_t)b * Tt + t) * Vv + v] = acc + b_score[v];
    }
}

// ---------------- launch ----------------
extern "C" void kernel_launch(void* const* d_in, const int* in_sizes, int n_in,
                              void* d_out, int out_size) {
    const int*   labels  = (const int*)  d_in[0];
    const float* keys    = (const float*)d_in[1];
    const float* values  = (const float*)d_in[2];
    const float* emb     = (const float*)d_in[3];
    const float* w_ih0   = (const float*)d_in[4];
    const float* w_hh0   = (const float*)d_in[5];
    const float* b_ih0   = (const float*)d_in[6];
    const float* b_hh0   = (const float*)d_in[7];
    const float* w_ih1   = (const float*)d_in[8];
    const float* w_hh1   = (const float*)d_in[9];
    const float* b_ih1   = (const float*)d_in[10];
    const float* b_hh1   = (const float*)d_in[11];
    const float* w_ih2   = (const float*)d_in[12];
    const float* w_hh2   = (const float*)d_in[13];
    const float* b_ih2   = (const float*)d_in[14];
    const float* b_hh2   = (const float*)d_in[15];
    const float* w_proj  = (const float*)d_in[16];
    const float* b_proj  = (const float*)d_in[17];
    const float* w_score = (const float*)d_in[18];
    const float* b_score = (const float*)d_in[19];
    const float* h0      = (const float*)d_in[20];

    float* out_pred = (float*)d_out;
    float* out_attn = out_pred + (size_t)Bsz * Tt * Vv;

    cudaFuncSetAttribute(lstm_mma_kernel,
                         cudaFuncAttributeMaxDynamicSharedMemorySize, LSTM_SMEM);

    {
        // weight conversion (runs every replay; ~40us total)
        float* wc0; float* wc1; float* wc2;
        cudaGetSymbolAddress((void**)&wc0, g_wcat);
        wc1 = wc0 + (size_t)4096 * 2048;
        wc2 = wc1 + (size_t)4096 * 2048;
        convert_w_kernel<<<4096, 256>>>(w_ih0, w_hh0, wc0);
        convert_w_kernel<<<4096, 256>>>(w_ih1, w_hh1, wc1);
        convert_w_kernel<<<4096, 256>>>(w_ih2, w_hh2, wc2);
    }

    embed_kernel<<<Tt * Bsz, 128>>>(labels, emb);
    init_state_kernel<<<(Bsz * Hh + 255) / 256, 256>>>(h0);
    init_ctx_kernel<<<Kk, 256>>>(h0, w_proj, b_proj);

    for (int t = 0; t < Tt; t++) {
        lstm_mma_kernel<<<128, 256, LSTM_SMEM>>>(0, t, b_ih0, b_hh0);
        lstm_mma_kernel<<<128, 256, LSTM_SMEM>>>(1, t, b_ih1, b_hh1);
        lstm_mma_kernel<<<128, 256, LSTM_SMEM>>>(2, t, b_ih2, b_hh2);
        proj_q_kernel<<<64, 256>>>(t, w_proj, b_proj);
        energy_kernel<<<dim3(64, 8), 256>>>(keys);
        softmax_kernel<<<64, 512>>>(t, out_attn);
        ctx_kernel<<<dim3(4, 64), 128>>>(t, values, out_attn);
        score_kernel<<<64, 256>>>(t, w_score, b_score, out_pred);
    }
}

// round 6
// speedup vs baseline: 2.5959x; 1.1635x over previous
#include <cuda_runtime.h>
#include <cuda_bf16.h>
#include <math.h>
#include <stdint.h>
#include <stddef.h>

#define Bsz 64
#define Tt  100
#define Ss  400
#define Ee  512
#define Hh  1024
#define Kk  512
#define Vv  34

typedef __nv_bfloat16 bf16;

// ---------------- static device scratch ----------------
__device__ __align__(256) bf16  g_wcat[3][(size_t)4096 * 2048];  // bf16 weights, concat ih|hh
__device__ __align__(256) bf16  g_xs[(size_t)Tt * Bsz * Ee];     // bf16 embedded inputs
__device__ __align__(256) bf16  g_h1b[2][Bsz * Hh];              // bf16 h states (ping-pong)
__device__ __align__(256) bf16  g_h2b[2][Bsz * Hh];
__device__ __align__(256) bf16  g_h3b[2][Bsz * Hh];
__device__ __align__(256) float g_h3f[2][Bsz * Hh];              // fp32 h3 (for proj)
__device__ __align__(256) float g_c1[Bsz * Hh];
__device__ __align__(256) float g_c2[Bsz * Hh];
__device__ __align__(256) float g_c3[Bsz * Hh];
__device__ __align__(256) float g_ctx[Bsz * Kk];                 // fp32 (score)
__device__ __align__(256) bf16  g_ctxb[Bsz * Kk];                // bf16 (gemm)
__device__ __align__(256) float g_q[Bsz * Kk];
__device__ __align__(256) float g_energy[Bsz * Ss];

// ---------------- helpers ----------------
__device__ __forceinline__ void cpa16(uint32_t dst, const void* src) {
    asm volatile("cp.async.ca.shared.global [%0], [%1], 16;\n" :: "r"(dst), "l"(src));
}
#define CPA_COMMIT() asm volatile("cp.async.commit_group;\n" ::: "memory")
#define CPA_WAIT(n)  asm volatile("cp.async.wait_group %0;\n" :: "n"(n) : "memory")

__device__ __forceinline__ void mma_bf16(float* c,
    uint32_t a0, uint32_t a1, uint32_t a2, uint32_t a3,
    uint32_t b0, uint32_t b1) {
    asm volatile(
        "mma.sync.aligned.m16n8k16.row.col.f32.bf16.bf16.f32 "
        "{%0,%1,%2,%3},{%4,%5,%6,%7},{%8,%9},{%0,%1,%2,%3};\n"
        : "+f"(c[0]), "+f"(c[1]), "+f"(c[2]), "+f"(c[3])
        : "r"(a0), "r"(a1), "r"(a2), "r"(a3), "r"(b0), "r"(b1));
}

// ---------------- weight conversion (fp32 -> bf16, concat ih|hh) ----------------
__global__ void convert_w_kernel(const float* __restrict__ w_ih,
                                 const float* __restrict__ w_hh,
                                 bf16* __restrict__ dst) {
    int r = blockIdx.x;                     // 0..4095
    int i = threadIdx.x;                    // 0..255
    float4 va = ((const float4*)(w_ih + (size_t)r * 1024))[i];
    float4 vb = ((const float4*)(w_hh + (size_t)r * 1024))[i];
    __nv_bfloat162* d2 = (__nv_bfloat162*)(dst + (size_t)r * 2048);
    d2[2 * i]           = __floats2bfloat162_rn(va.x, va.y);
    d2[2 * i + 1]       = __floats2bfloat162_rn(va.z, va.w);
    d2[512 + 2 * i]     = __floats2bfloat162_rn(vb.x, vb.y);
    d2[512 + 2 * i + 1] = __floats2bfloat162_rn(vb.z, vb.w);
}

// ---------------- embedding gather (stores bf16) ----------------
__global__ void embed_kernel(const int* __restrict__ labels,
                             const float* __restrict__ emb) {
    int tb = blockIdx.x;
    int t = tb / Bsz;
    int b = tb % Bsz;
    int lab = labels[b * Tt + t];
    const float4* src = (const float4*)(emb + (size_t)lab * Ee);
    __nv_bfloat162* dst = (__nv_bfloat162*)(g_xs + ((size_t)t * Bsz + b) * Ee);
    for (int i = threadIdx.x; i < Ee / 4; i += blockDim.x) {
        float4 v = src[i];
        dst[2 * i]     = __floats2bfloat162_rn(v.x, v.y);
        dst[2 * i + 1] = __floats2bfloat162_rn(v.z, v.w);
    }
}

// ---------------- init h/c ----------------
__global__ void init_state_kernel(const float* __restrict__ h0) {
    int i = blockIdx.x * blockDim.x + threadIdx.x;
    if (i < Bsz * Hh) {
        float v = h0[i % Hh];
        bf16 vb = __float2bfloat16_rn(v);
        g_h1b[0][i] = vb; g_h2b[0][i] = vb; g_h3b[0][i] = vb;
        g_h3f[0][i] = v;
        g_c1[i] = v; g_c2[i] = v; g_c3[i] = v;
    }
}

// ---------------- init ctx0 ----------------
__global__ void init_ctx_kernel(const float* __restrict__ h0,
                                const float* __restrict__ w_proj,
                                const float* __restrict__ b_proj) {
    int k = blockIdx.x;
    __shared__ float red[256];
    float s = 0.f;
    for (int i = threadIdx.x; i < Hh; i += 256)
        s += h0[i] * w_proj[(size_t)k * Hh + i];
    red[threadIdx.x] = s;
    __syncthreads();
    for (int off = 128; off; off >>= 1) {
        if (threadIdx.x < off) red[threadIdx.x] += red[threadIdx.x + off];
        __syncthreads();
    }
    float v = red[0] + b_proj[k];
    if (threadIdx.x < Bsz) {
        g_ctx[(size_t)threadIdx.x * Kk + k]  = v;
        g_ctxb[(size_t)threadIdx.x * Kk + k] = __float2bfloat16_rn(v);
    }
}

// ---------------- bf16 MMA LSTM cell ----------------
// C[64 x 4096] = A[64 x 2048] @ Wcat^T ; block owns 8 j x 4 gates (N=32 cols),
// grid = 128 blocks, 256 threads (8 warps: 4 m-tiles x 2 n-halves).
#define BK 64
#define STAGES 3
#define APAD 72                      // bf16 elements per row (64 + 8 pad)
#define A_ST (64 * APAD)             // bf16 elements
#define B_ST (32 * APAD)
#define STAGE_ELE (A_ST + B_ST)      // 6912 bf16 = 13824 B
#define LSTM_SMEM (STAGES * STAGE_ELE * 2)

struct SegInfo { const bf16* p; int stride; };

__device__ __forceinline__ SegInfo a_seg(int cell, int p, int t, int seg) {
    SegInfo r;
    if (cell == 0) {
        if (seg == 0)      { r.p = g_xs + (size_t)t * Bsz * Ee; r.stride = Ee; }
        else if (seg == 1) { r.p = g_ctxb;                      r.stride = Kk; }
        else               { r.p = g_h1b[p] + (seg - 2) * 512;  r.stride = Hh; }
    } else if (cell == 1) {
        if (seg < 2) { r.p = g_h1b[1 - p] + seg * 512;       r.stride = Hh; }
        else         { r.p = g_h2b[p]     + (seg - 2) * 512; r.stride = Hh; }
    } else {
        if (seg < 2) { r.p = g_h2b[1 - p] + seg * 512;       r.stride = Hh; }
        else         { r.p = g_h3b[p]     + (seg - 2) * 512; r.stride = Hh; }
    }
    return r;
}

__global__ void __launch_bounds__(256) lstm_mma_kernel(
    int cell, int t,
    const float* __restrict__ b_ih, const float* __restrict__ b_hh)
{
    extern __shared__ __align__(16) char smem_raw[];
    bf16* smem = (bf16*)smem_raw;
    const int p = t & 1;
    const int tid = threadIdx.x;
    const int lane = tid & 31;
    const int warp = tid >> 5;
    const int wm = warp & 3;
    const int wn = warp >> 2;
    const int j0 = blockIdx.x * 8;
    const bf16* __restrict__ wcat = g_wcat[cell];

    float* c_st; bf16* h_ob; float* h_f;
    if (cell == 0)      { c_st = g_c1; h_ob = g_h1b[1 - p]; h_f = nullptr; }
    else if (cell == 1) { c_st = g_c2; h_ob = g_h2b[1 - p]; h_f = nullptr; }
    else                { c_st = g_c3; h_ob = g_h3b[1 - p]; h_f = g_h3f[1 - p]; }

    const uint32_t smem_u = (uint32_t)__cvta_generic_to_shared(smem);

    float acc0[4] = {0.f, 0.f, 0.f, 0.f};
    float acc1[4] = {0.f, 0.f, 0.f, 0.f};

    const int NTILES = 2048 / BK;   // 32

    // ---- tile issue: A 64x64 bf16 (512 x 16B), B 32x64 bf16 (256 x 16B) ----
    auto issue_tile = [&](int kt, int ss) {
        const int k0 = kt * BK;
        SegInfo si = a_seg(cell, p, t, k0 >> 9);
        const int kin = k0 & 511;
        const uint32_t abase = smem_u + (uint32_t)(ss * STAGE_ELE) * 2u;
        const uint32_t bbase = abase + (uint32_t)A_ST * 2u;
#pragma unroll
        for (int j = 0; j < 2; j++) {            // A: 512 chunks of 8 bf16
            int i = tid + j * 256;
            int m = i >> 3, c8 = i & 7;
            const bf16* src = si.p + (size_t)m * si.stride + kin + c8 * 8;
            cpa16(abase + (uint32_t)(m * APAD + c8 * 8) * 2u, src);
        }
        {                                        // B: 256 chunks of 8 bf16
            int n = tid >> 3, c8 = tid & 7;
            int r = (n >> 3) * 1024 + j0 + (n & 7);
            const bf16* src = wcat + (size_t)r * 2048 + k0 + c8 * 8;
            cpa16(bbase + (uint32_t)(n * APAD + c8 * 8) * 2u, src);
        }
    };

    issue_tile(0, 0); CPA_COMMIT();
    issue_tile(1, 1); CPA_COMMIT();

    const int ar = lane >> 2;   // 0..7
    const int ac = lane & 3;    // 0..3
    const int arow = wm * 16 + ar;

    for (int kt = 0; kt < NTILES; kt++) {
        if (kt + 2 < NTILES) issue_tile(kt + 2, (kt + 2) % STAGES);
        CPA_COMMIT();
        CPA_WAIT(2);
        __syncthreads();

        const bf16* As = smem + (kt % STAGES) * STAGE_ELE;
        const bf16* Bs = As + A_ST;
#pragma unroll
        for (int ks = 0; ks < BK / 16; ks++) {
            const int kb = ks * 16;
            uint32_t a0 = *(const uint32_t*)&As[arow * APAD + kb + 2 * ac];
            uint32_t a1 = *(const uint32_t*)&As[(arow + 8) * APAD + kb + 2 * ac];
            uint32_t a2 = *(const uint32_t*)&As[arow * APAD + kb + 8 + 2 * ac];
            uint32_t a3 = *(const uint32_t*)&As[(arow + 8) * APAD + kb + 8 + 2 * ac];
            {
                int n = wn * 16 + ar;
                uint32_t b0 = *(const uint32_t*)&Bs[n * APAD + kb + 2 * ac];
                uint32_t b1 = *(const uint32_t*)&Bs[n * APAD + kb + 8 + 2 * ac];
                mma_bf16(acc0, a0, a1, a2, a3, b0, b1);
            }
            {
                int n = wn * 16 + 8 + ar;
                uint32_t b0 = *(const uint32_t*)&Bs[n * APAD + kb + 2 * ac];
                uint32_t b1 = *(const uint32_t*)&Bs[n * APAD + kb + 8 + 2 * ac];
                mma_bf16(acc1, a0, a1, a2, a3, b0, b1);
            }
        }
        __syncthreads();
    }
    CPA_WAIT(0);

    // ---- stage C through smem: Cs[64][33] floats, col n = g*8 + jj ----
    float* Cs = (float*)smem_raw;
    {
        int crow = wm * 16 + ar;
        int cc0 = wn * 16 + 2 * ac;
        Cs[crow * 33 + cc0]           = acc0[0];
        Cs[crow * 33 + cc0 + 1]       = acc0[1];
        Cs[(crow + 8) * 33 + cc0]     = acc0[2];
        Cs[(crow + 8) * 33 + cc0 + 1] = acc0[3];
        Cs[crow * 33 + cc0 + 8]       = acc1[0];
        Cs[crow * 33 + cc0 + 9]       = acc1[1];
        Cs[(crow + 8) * 33 + cc0 + 8] = acc1[2];
        Cs[(crow + 8) * 33 + cc0 + 9] = acc1[3];
    }
    __syncthreads();

    // ---- fused LSTM update: 512 (m, jj) pairs, 2 per thread ----
#pragma unroll
    for (int j = 0; j < 2; j++) {
        int pr = tid + j * 256;
        int m = pr & 63;
        int jj = pr >> 6;
        int jg = j0 + jj;
        float gi = Cs[m * 33 + jj]      + b_ih[jg]        + b_hh[jg];
        float gf = Cs[m * 33 + 8 + jj]  + b_ih[1024 + jg] + b_hh[1024 + jg];
        float gg = Cs[m * 33 + 16 + jj] + b_ih[2048 + jg] + b_hh[2048 + jg];
        float go = Cs[m * 33 + 24 + jj] + b_ih[3072 + jg] + b_hh[3072 + jg];
        float si = 1.f / (1.f + expf(-gi));
        float sf = 1.f / (1.f + expf(-gf));
        float so = 1.f / (1.f + expf(-go));
        float cn = sf * c_st[(size_t)m * Hh + jg] + si * tanhf(gg);
        c_st[(size_t)m * Hh + jg] = cn;
        float hn = so * tanhf(cn);
        h_ob[(size_t)m * Hh + jg] = __float2bfloat16_rn(hn);
        if (h_f) h_f[(size_t)m * Hh + jg] = hn;
    }
}

// ---------------- q = h3 @ w_proj^T + b_proj (smem-tiled) ----------------
__global__ void __launch_bounds__(256) proj_q_kernel(
    int t, const float* __restrict__ w_proj, const float* __restrict__ b_proj)
{
    __shared__ float sw[8 * 1024];
    const int tid = threadIdx.x;
    const int kb = blockIdx.x;
    const float4* wp4 = (const float4*)(w_proj + (size_t)kb * 8 * 1024);
    float4* sw4 = (float4*)sw;
#pragma unroll
    for (int j = 0; j < 8; j++) sw4[tid + j * 256] = wp4[tid + j * 256];
    __syncthreads();

    const float* h3 = g_h3f[1 - (t & 1)];
    int b = tid >> 2;
    int kl = tid & 3;
    const float4* hr = (const float4*)(h3 + (size_t)b * Hh);
    const float4* w0 = (const float4*)(sw + kl * 1024);
    const float4* w1 = (const float4*)(sw + (kl + 4) * 1024);
    float a0 = 0.f, a1 = 0.f;
#pragma unroll 4
    for (int i = 0; i < 256; i++) {
        float4 h4 = hr[i];
        float4 x0 = w0[i];
        float4 x1 = w1[i];
        a0 += h4.x * x0.x + h4.y * x0.y + h4.z * x0.z + h4.w * x0.w;
        a1 += h4.x * x1.x + h4.y * x1.y + h4.z * x1.z + h4.w * x1.w;
    }
    int kg = kb * 8 + kl;
    g_q[(size_t)b * Kk + kg]     = a0 + b_proj[kg];
    g_q[(size_t)b * Kk + kg + 4] = a1 + b_proj[kg + 4];
}

// ---------------- energy: grid (64 b, 8 s-chunks), 256 threads ----------------
__global__ void __launch_bounds__(256) energy_kernel(const float* __restrict__ keys) {
    const int b = blockIdx.x;
    const int sc = blockIdx.y;
    const int tid = threadIdx.x;
    const int lane = tid & 31;
    const int wid = tid >> 5;
    __shared__ float sq[Kk];
    if (tid < 128)
        ((float4*)sq)[tid] = ((const float4*)(g_q + (size_t)b * Kk))[tid];
    __syncthreads();
    const float4* qr = (const float4*)sq;
    for (int s = sc * 50 + wid; s < sc * 50 + 50; s += 8) {
        const float4* kr = (const float4*)(keys + ((size_t)s * Bsz + b) * Kk);
        float acc = 0.f;
#pragma unroll
        for (int i = 0; i < 4; i++) {
            float4 k4 = kr[lane + i * 32];
            float4 q4 = qr[lane + i * 32];
            acc += k4.x * q4.x + k4.y * q4.y + k4.z * q4.z + k4.w * q4.w;
        }
#pragma unroll
        for (int off = 16; off; off >>= 1)
            acc += __shfl_xor_sync(0xffffffffu, acc, off);
        if (lane == 0) g_energy[b * Ss + s] = acc;
    }
}

// ---------------- softmax: grid 64, 512 threads ----------------
__global__ void __launch_bounds__(512) softmax_kernel(int t, float* __restrict__ out_attn) {
    const int b = blockIdx.x;
    const int tid = threadIdx.x;
    const int lane = tid & 31;
    const int wid = tid >> 5;
    __shared__ float se[Ss];
    __shared__ float red[16];
    for (int s = tid; s < Ss; s += 512) se[s] = g_energy[b * Ss + s];
    __syncthreads();

    float m = -3.4e38f;
    for (int s = tid; s < Ss; s += 512) m = fmaxf(m, se[s]);
#pragma unroll
    for (int off = 16; off; off >>= 1)
        m = fmaxf(m, __shfl_xor_sync(0xffffffffu, m, off));
    if (lane == 0) red[wid] = m;
    __syncthreads();
    if (wid == 0) {
        float v = (lane < 16) ? red[lane] : -3.4e38f;
#pragma unroll
        for (int off = 8; off; off >>= 1)
            v = fmaxf(v, __shfl_xor_sync(0xffffffffu, v, off));
        if (lane == 0) red[0] = v;
    }
    __syncthreads();
    const float mx = red[0];
    __syncthreads();

    float sum = 0.f;
    for (int s = tid; s < Ss; s += 512) {
        float e = expf(se[s] - mx);
        se[s] = e;
        sum += e;
    }
#pragma unroll
    for (int off = 16; off; off >>= 1)
        sum += __shfl_xor_sync(0xffffffffu, sum, off);
    if (lane == 0) red[wid] = sum;
    __syncthreads();
    if (wid == 0) {
        float v = (lane < 16) ? red[lane] : 0.f;
#pragma unroll
        for (int off = 8; off; off >>= 1)
            v += __shfl_xor_sync(0xffffffffu, v, off);
        if (lane == 0) red[0] = v;
    }
    __syncthreads();
    const float inv = 1.f / red[0];
    for (int s = tid; s < Ss; s += 512)
        out_attn[((size_t)b * Tt + t) * Ss + s] = se[s] * inv;
}

// ---------------- ctx: grid (4 k-chunks, 64 b), 128 threads ----------------
__global__ void __launch_bounds__(128) ctx_kernel(
    int t, const float* __restrict__ values, const float* __restrict__ out_attn)
{
    const int kc = blockIdx.x;
    const int b = blockIdx.y;
    const int tid = threadIdx.x;
    __shared__ float sat[Ss];
    const float* ap = out_attn + ((size_t)b * Tt + t) * Ss;
    for (int i = tid; i < Ss; i += 128) sat[i] = ap[i];
    __syncthreads();

    const int k = kc * 128 + tid;
    const size_t base = (size_t)b * Kk + k;
    const size_t str = (size_t)Bsz * Kk;
    float a0 = 0.f, a1 = 0.f, a2 = 0.f, a3 = 0.f;
    for (int s = 0; s < Ss; s += 4) {
        a0 += sat[s]     * values[base + (size_t)s * str];
        a1 += sat[s + 1] * values[base + (size_t)(s + 1) * str];
        a2 += sat[s + 2] * values[base + (size_t)(s + 2) * str];
        a3 += sat[s + 3] * values[base + (size_t)(s + 3) * str];
    }
    float r = (a0 + a1) + (a2 + a3);
    g_ctx[(size_t)b * Kk + k]  = r;
    g_ctxb[(size_t)b * Kk + k] = __float2bfloat16_rn(r);
}

// ---------------- score: grid 64, 256 threads ----------------
__global__ void __launch_bounds__(256) score_kernel(
    int t, const float* __restrict__ w_score, const float* __restrict__ b_score,
    float* __restrict__ out_pred)
{
    const int b = blockIdx.x;
    const int tid = threadIdx.x;
    const int lane = tid & 31;
    const int wid = tid >> 5;
    __shared__ float sq[Kk];
    __shared__ float sc[Kk];
    for (int i = tid; i < Kk; i += 256) {
        sq[i] = g_q[(size_t)b * Kk + i];
        sc[i] = g_ctx[(size_t)b * Kk + i];
    }
    __syncthreads();
    for (int v = wid; v < Vv; v += 8) {
        const float* wr = w_score + (size_t)v * (2 * Kk);
        float acc = 0.f;
        for (int i = lane; i < Kk; i += 32)
            acc += sq[i] * wr[i] + sc[i] * wr[Kk + i];
#pragma unroll
        for (int off = 16; off; off >>= 1)
            acc += __shfl_xor_sync(0xffffffffu, acc, off);
        if (lane == 0)
            out_pred[((size_t)b * Tt + t) * Vv + v] = acc + b_score[v];
    }
}

// ---------------- launch ----------------
extern "C" void kernel_launch(void* const* d_in, const int* in_sizes, int n_in,
                              void* d_out, int out_size) {
    const int*   labels  = (const int*)  d_in[0];
    const float* keys    = (const float*)d_in[1];
    const float* values  = (const float*)d_in[2];
    const float* emb     = (const float*)d_in[3];
    const float* w_ih0   = (const float*)d_in[4];
    const float* w_hh0   = (const float*)d_in[5];
    const float* b_ih0   = (const float*)d_in[6];
    const float* b_hh0   = (const float*)d_in[7];
    const float* w_ih1   = (const float*)d_in[8];
    const float* w_hh1   = (const float*)d_in[9];
    const float* b_ih1   = (const float*)d_in[10];
    const float* b_hh1   = (const float*)d_in[11];
    const float* w_ih2   = (const float*)d_in[12];
    const float* w_hh2   = (const float*)d_in[13];
    const float* b_ih2   = (const float*)d_in[14];
    const float* b_hh2   = (const float*)d_in[15];
    const float* w_proj  = (const float*)d_in[16];
    const float* b_proj  = (const float*)d_in[17];
    const float* w_score = (const float*)d_in[18];
    const float* b_score = (const float*)d_in[19];
    const float* h0      = (const float*)d_in[20];

    float* out_pred = (float*)d_out;
    float* out_attn = out_pred + (size_t)Bsz * Tt * Vv;

    cudaFuncSetAttribute(lstm_mma_kernel,
                         cudaFuncAttributeMaxDynamicSharedMemorySize, LSTM_SMEM);

    {
        bf16* wc0;
        cudaGetSymbolAddress((void**)&wc0, g_wcat);
        bf16* wc1 = wc0 + (size_t)4096 * 2048;
        bf16* wc2 = wc1 + (size_t)4096 * 2048;
        convert_w_kernel<<<4096, 256>>>(w_ih0, w_hh0, wc0);
        convert_w_kernel<<<4096, 256>>>(w_ih1, w_hh1, wc1);
        convert_w_kernel<<<4096, 256>>>(w_ih2, w_hh2, wc2);
    }

    embed_kernel<<<Tt * Bsz, 128>>>(labels, emb);
    init_state_kernel<<<(Bsz * Hh + 255) / 256, 256>>>(h0);
    init_ctx_kernel<<<Kk, 256>>>(h0, w_proj, b_proj);

    for (int t = 0; t < Tt; t++) {
        lstm_mma_kernel<<<128, 256, LSTM_SMEM>>>(0, t, b_ih0, b_hh0);
        lstm_mma_kernel<<<128, 256, LSTM_SMEM>>>(1, t, b_ih1, b_hh1);
        lstm_mma_kernel<<<128, 256, LSTM_SMEM>>>(2, t, b_ih2, b_hh2);
        proj_q_kernel<<<64, 256>>>(t, w_proj, b_proj);
        energy_kernel<<<dim3(64, 8), 256>>>(keys);
        softmax_kernel<<<64, 512>>>(t, out_attn);
        ctx_kernel<<<dim3(4, 64), 128>>>(t, values, out_attn);
        score_kernel<<<64, 256>>>(t, w_score, b_score, out_pred);
    }
}

// round 7
// speedup vs baseline: 3.0074x; 1.1585x over previous
#include <cuda_runtime.h>
#include <cuda_bf16.h>
#include <math.h>
#include <stdint.h>
#include <stddef.h>

#define Bsz 64
#define Tt  100
#define Ss  400
#define Ee  512
#define Hh  1024
#define Kk  512
#define Vv  34

typedef __nv_bfloat16 bf16;

// ---------------- static device scratch ----------------
__device__ __align__(256) bf16  g_wcat[3][(size_t)4096 * 2048];  // bf16 weights, concat ih|hh
__device__ __align__(256) bf16  g_xs[(size_t)Tt * Bsz * Ee];     // bf16 embedded inputs
__device__ __align__(256) bf16  g_h1b[2][Bsz * Hh];              // bf16 h states (ping-pong)
__device__ __align__(256) bf16  g_h2b[2][Bsz * Hh];
__device__ __align__(256) bf16  g_h3b[2][Bsz * Hh];
__device__ __align__(256) float g_h3f[2][Bsz * Hh];              // fp32 h3 (for proj)
__device__ __align__(256) float g_c1[Bsz * Hh];
__device__ __align__(256) float g_c2[Bsz * Hh];
__device__ __align__(256) float g_c3[Bsz * Hh];
__device__ __align__(256) bf16  g_ctxb[Bsz * Kk];                // bf16 (gemm)
__device__ __align__(256) float g_q[Bsz * Kk];
__device__ __align__(256) float g_energy[Bsz * Ss];

// ---------------- helpers ----------------
__device__ __forceinline__ void cpa16(uint32_t dst, const void* src) {
    asm volatile("cp.async.ca.shared.global [%0], [%1], 16;\n" :: "r"(dst), "l"(src));
}
#define CPA_COMMIT() asm volatile("cp.async.commit_group;\n" ::: "memory")
#define CPA_WAIT(n)  asm volatile("cp.async.wait_group %0;\n" :: "n"(n) : "memory")

__device__ __forceinline__ void mma_bf16(float* c,
    uint32_t a0, uint32_t a1, uint32_t a2, uint32_t a3,
    uint32_t b0, uint32_t b1) {
    asm volatile(
        "mma.sync.aligned.m16n8k16.row.col.f32.bf16.bf16.f32 "
        "{%0,%1,%2,%3},{%4,%5,%6,%7},{%8,%9},{%0,%1,%2,%3};\n"
        : "+f"(c[0]), "+f"(c[1]), "+f"(c[2]), "+f"(c[3])
        : "r"(a0), "r"(a1), "r"(a2), "r"(a3), "r"(b0), "r"(b1));
}

// ---------------- weight conversion (fp32 -> bf16, concat ih|hh) ----------------
__global__ void convert_w_kernel(const float* __restrict__ w_ih,
                                 const float* __restrict__ w_hh,
                                 bf16* __restrict__ dst) {
    int r = blockIdx.x;                     // 0..4095
    int i = threadIdx.x;                    // 0..255
    float4 va = ((const float4*)(w_ih + (size_t)r * 1024))[i];
    float4 vb = ((const float4*)(w_hh + (size_t)r * 1024))[i];
    __nv_bfloat162* d2 = (__nv_bfloat162*)(dst + (size_t)r * 2048);
    d2[2 * i]           = __floats2bfloat162_rn(va.x, va.y);
    d2[2 * i + 1]       = __floats2bfloat162_rn(va.z, va.w);
    d2[512 + 2 * i]     = __floats2bfloat162_rn(vb.x, vb.y);
    d2[512 + 2 * i + 1] = __floats2bfloat162_rn(vb.z, vb.w);
}

// ---------------- embedding gather (stores bf16) ----------------
__global__ void embed_kernel(const int* __restrict__ labels,
                             const float* __restrict__ emb) {
    int tb = blockIdx.x;
    int t = tb / Bsz;
    int b = tb % Bsz;
    int lab = labels[b * Tt + t];
    const float4* src = (const float4*)(emb + (size_t)lab * Ee);
    __nv_bfloat162* dst = (__nv_bfloat162*)(g_xs + ((size_t)t * Bsz + b) * Ee);
    for (int i = threadIdx.x; i < Ee / 4; i += blockDim.x) {
        float4 v = src[i];
        dst[2 * i]     = __floats2bfloat162_rn(v.x, v.y);
        dst[2 * i + 1] = __floats2bfloat162_rn(v.z, v.w);
    }
}

// ---------------- init h/c ----------------
__global__ void init_state_kernel(const float* __restrict__ h0) {
    int i = blockIdx.x * blockDim.x + threadIdx.x;
    if (i < Bsz * Hh) {
        float v = h0[i % Hh];
        bf16 vb = __float2bfloat16_rn(v);
        g_h1b[0][i] = vb; g_h2b[0][i] = vb; g_h3b[0][i] = vb;
        g_h3f[0][i] = v;
        g_c1[i] = v; g_c2[i] = v; g_c3[i] = v;
    }
}

// ---------------- init ctx0 ----------------
__global__ void init_ctx_kernel(const float* __restrict__ h0,
                                const float* __restrict__ w_proj,
                                const float* __restrict__ b_proj) {
    int k = blockIdx.x;
    __shared__ float red[256];
    float s = 0.f;
    for (int i = threadIdx.x; i < Hh; i += 256)
        s += h0[i] * w_proj[(size_t)k * Hh + i];
    red[threadIdx.x] = s;
    __syncthreads();
    for (int off = 128; off; off >>= 1) {
        if (threadIdx.x < off) red[threadIdx.x] += red[threadIdx.x + off];
        __syncthreads();
    }
    float v = red[0] + b_proj[k];
    if (threadIdx.x < Bsz)
        g_ctxb[(size_t)threadIdx.x * Kk + k] = __float2bfloat16_rn(v);
}

// ---------------- bf16 MMA LSTM cell ----------------
// C[64 x 4096] = A[64 x 2048] @ Wcat^T ; block owns 8 j x 4 gates (N=32 cols),
// grid = 128 blocks, 256 threads (8 warps: 4 m-tiles x 2 n-halves).
// 5-stage cp.async pipeline, prefetch distance 4.
#define BK 64
#define STAGES 5
#define PFD 4
#define APAD 72                      // bf16 elements per row (64 + 8 pad)
#define A_ST (64 * APAD)             // bf16 elements
#define B_ST (32 * APAD)
#define STAGE_ELE (A_ST + B_ST)      // 6912 bf16 = 13824 B
#define LSTM_SMEM (STAGES * STAGE_ELE * 2)

struct SegInfo { const bf16* p; int stride; };

__device__ __forceinline__ SegInfo a_seg(int cell, int p, int t, int seg) {
    SegInfo r;
    if (cell == 0) {
        if (seg == 0)      { r.p = g_xs + (size_t)t * Bsz * Ee; r.stride = Ee; }
        else if (seg == 1) { r.p = g_ctxb;                      r.stride = Kk; }
        else               { r.p = g_h1b[p] + (seg - 2) * 512;  r.stride = Hh; }
    } else if (cell == 1) {
        if (seg < 2) { r.p = g_h1b[1 - p] + seg * 512;       r.stride = Hh; }
        else         { r.p = g_h2b[p]     + (seg - 2) * 512; r.stride = Hh; }
    } else {
        if (seg < 2) { r.p = g_h2b[1 - p] + seg * 512;       r.stride = Hh; }
        else         { r.p = g_h3b[p]     + (seg - 2) * 512; r.stride = Hh; }
    }
    return r;
}

__global__ void __launch_bounds__(256) lstm_mma_kernel(
    int cell, int t,
    const float* __restrict__ b_ih, const float* __restrict__ b_hh)
{
    extern __shared__ __align__(16) char smem_raw[];
    bf16* smem = (bf16*)smem_raw;
    const int p = t & 1;
    const int tid = threadIdx.x;
    const int lane = tid & 31;
    const int warp = tid >> 5;
    const int wm = warp & 3;
    const int wn = warp >> 2;
    const int j0 = blockIdx.x * 8;
    const bf16* __restrict__ wcat = g_wcat[cell];

    float* c_st; bf16* h_ob; float* h_f;
    if (cell == 0)      { c_st = g_c1; h_ob = g_h1b[1 - p]; h_f = nullptr; }
    else if (cell == 1) { c_st = g_c2; h_ob = g_h2b[1 - p]; h_f = nullptr; }
    else                { c_st = g_c3; h_ob = g_h3b[1 - p]; h_f = g_h3f[1 - p]; }

    const uint32_t smem_u = (uint32_t)__cvta_generic_to_shared(smem);

    float acc0[4] = {0.f, 0.f, 0.f, 0.f};
    float acc1[4] = {0.f, 0.f, 0.f, 0.f};

    const int NTILES = 2048 / BK;   // 32

    auto issue_tile = [&](int kt, int ss) {
        const int k0 = kt * BK;
        SegInfo si = a_seg(cell, p, t, k0 >> 9);
        const int kin = k0 & 511;
        const uint32_t abase = smem_u + (uint32_t)(ss * STAGE_ELE) * 2u;
        const uint32_t bbase = abase + (uint32_t)A_ST * 2u;
#pragma unroll
        for (int j = 0; j < 2; j++) {            // A: 512 chunks of 8 bf16
            int i = tid + j * 256;
            int m = i >> 3, c8 = i & 7;
            const bf16* src = si.p + (size_t)m * si.stride + kin + c8 * 8;
            cpa16(abase + (uint32_t)(m * APAD + c8 * 8) * 2u, src);
        }
        {                                        // B: 256 chunks of 8 bf16
            int n = tid >> 3, c8 = tid & 7;
            int r = (n >> 3) * 1024 + j0 + (n & 7);
            const bf16* src = wcat + (size_t)r * 2048 + k0 + c8 * 8;
            cpa16(bbase + (uint32_t)(n * APAD + c8 * 8) * 2u, src);
        }
    };

    // prologue: prefetch PFD tiles
#pragma unroll
    for (int i = 0; i < PFD; i++) { issue_tile(i, i); CPA_COMMIT(); }

    const int ar = lane >> 2;   // 0..7
    const int ac = lane & 3;    // 0..3
    const int arow = wm * 16 + ar;

    for (int kt = 0; kt < NTILES; kt++) {
        if (kt + PFD < NTILES) issue_tile(kt + PFD, (kt + PFD) % STAGES);
        CPA_COMMIT();
        CPA_WAIT(PFD);
        __syncthreads();

        const bf16* As = smem + (kt % STAGES) * STAGE_ELE;
        const bf16* Bs = As + A_ST;
#pragma unroll
        for (int ks = 0; ks < BK / 16; ks++) {
            const int kb = ks * 16;
            uint32_t a0 = *(const uint32_t*)&As[arow * APAD + kb + 2 * ac];
            uint32_t a1 = *(const uint32_t*)&As[(arow + 8) * APAD + kb + 2 * ac];
            uint32_t a2 = *(const uint32_t*)&As[arow * APAD + kb + 8 + 2 * ac];
            uint32_t a3 = *(const uint32_t*)&As[(arow + 8) * APAD + kb + 8 + 2 * ac];
            {
                int n = wn * 16 + ar;
                uint32_t b0 = *(const uint32_t*)&Bs[n * APAD + kb + 2 * ac];
                uint32_t b1 = *(const uint32_t*)&Bs[n * APAD + kb + 8 + 2 * ac];
                mma_bf16(acc0, a0, a1, a2, a3, b0, b1);
            }
            {
                int n = wn * 16 + 8 + ar;
                uint32_t b0 = *(const uint32_t*)&Bs[n * APAD + kb + 2 * ac];
                uint32_t b1 = *(const uint32_t*)&Bs[n * APAD + kb + 8 + 2 * ac];
                mma_bf16(acc1, a0, a1, a2, a3, b0, b1);
            }
        }
        __syncthreads();
    }
    CPA_WAIT(0);

    // ---- stage C through smem: Cs[64][33] floats, col n = g*8 + jj ----
    float* Cs = (float*)smem_raw;
    {
        int crow = wm * 16 + ar;
        int cc0 = wn * 16 + 2 * ac;
        Cs[crow * 33 + cc0]           = acc0[0];
        Cs[crow * 33 + cc0 + 1]       = acc0[1];
        Cs[(crow + 8) * 33 + cc0]     = acc0[2];
        Cs[(crow + 8) * 33 + cc0 + 1] = acc0[3];
        Cs[crow * 33 + cc0 + 8]       = acc1[0];
        Cs[crow * 33 + cc0 + 9]       = acc1[1];
        Cs[(crow + 8) * 33 + cc0 + 8] = acc1[2];
        Cs[(crow + 8) * 33 + cc0 + 9] = acc1[3];
    }
    __syncthreads();

    // ---- fused LSTM update: 512 (m, jj) pairs, 2 per thread ----
#pragma unroll
    for (int j = 0; j < 2; j++) {
        int pr = tid + j * 256;
        int m = pr & 63;
        int jj = pr >> 6;
        int jg = j0 + jj;
        float gi = Cs[m * 33 + jj]      + b_ih[jg]        + b_hh[jg];
        float gf = Cs[m * 33 + 8 + jj]  + b_ih[1024 + jg] + b_hh[1024 + jg];
        float gg = Cs[m * 33 + 16 + jj] + b_ih[2048 + jg] + b_hh[2048 + jg];
        float go = Cs[m * 33 + 24 + jj] + b_ih[3072 + jg] + b_hh[3072 + jg];
        float si = 1.f / (1.f + expf(-gi));
        float sf = 1.f / (1.f + expf(-gf));
        float so = 1.f / (1.f + expf(-go));
        float cn = sf * c_st[(size_t)m * Hh + jg] + si * tanhf(gg);
        c_st[(size_t)m * Hh + jg] = cn;
        float hn = so * tanhf(cn);
        h_ob[(size_t)m * Hh + jg] = __float2bfloat16_rn(hn);
        if (h_f) h_f[(size_t)m * Hh + jg] = hn;
    }
}

// ---------------- q = h3 @ w_proj^T + b_proj (smem-tiled, 128 blocks) ----------------
__global__ void __launch_bounds__(256) proj_q_kernel(
    int t, const float* __restrict__ w_proj, const float* __restrict__ b_proj)
{
    __shared__ float sw[4 * 1024];
    const int tid = threadIdx.x;
    const int kb = blockIdx.x;           // 0..127, 4 k's each
    const float4* wp4 = (const float4*)(w_proj + (size_t)kb * 4 * 1024);
    float4* sw4 = (float4*)sw;
#pragma unroll
    for (int j = 0; j < 4; j++) sw4[tid + j * 256] = wp4[tid + j * 256];
    __syncthreads();

    const float* h3 = g_h3f[1 - (t & 1)];
    int b = tid >> 2;
    int kl = tid & 3;
    const float4* hr = (const float4*)(h3 + (size_t)b * Hh);
    const float4* w0 = (const float4*)(sw + kl * 1024);
    float a0 = 0.f, a1 = 0.f;
#pragma unroll 4
    for (int i = 0; i < 256; i += 2) {
        float4 h4 = hr[i];
        float4 x0 = w0[i];
        a0 += h4.x * x0.x + h4.y * x0.y + h4.z * x0.z + h4.w * x0.w;
        float4 h5 = hr[i + 1];
        float4 x1 = w0[i + 1];
        a1 += h5.x * x1.x + h5.y * x1.y + h5.z * x1.z + h5.w * x1.w;
    }
    int kg = kb * 4 + kl;
    g_q[(size_t)b * Kk + kg] = a0 + a1 + b_proj[kg];
}

// ---------------- energy: grid (64 b, 8 s-chunks), 256 threads ----------------
__global__ void __launch_bounds__(256) energy_kernel(const float* __restrict__ keys) {
    const int b = blockIdx.x;
    const int sc = blockIdx.y;
    const int tid = threadIdx.x;
    const int lane = tid & 31;
    const int wid = tid >> 5;
    __shared__ float sq[Kk];
    if (tid < 128)
        ((float4*)sq)[tid] = ((const float4*)(g_q + (size_t)b * Kk))[tid];
    __syncthreads();
    const float4* qr = (const float4*)sq;
    for (int s = sc * 50 + wid; s < sc * 50 + 50; s += 8) {
        const float4* kr = (const float4*)(keys + ((size_t)s * Bsz + b) * Kk);
        float acc = 0.f;
#pragma unroll
        for (int i = 0; i < 4; i++) {
            float4 k4 = kr[lane + i * 32];
            float4 q4 = qr[lane + i * 32];
            acc += k4.x * q4.x + k4.y * q4.y + k4.z * q4.z + k4.w * q4.w;
        }
#pragma unroll
        for (int off = 16; off; off >>= 1)
            acc += __shfl_xor_sync(0xffffffffu, acc, off);
        if (lane == 0) g_energy[b * Ss + s] = acc;
    }
}

// ---------------- fused softmax + ctx + score: grid 64, 512 threads ----------------
__global__ void __launch_bounds__(512) attn_fused_kernel(
    int t,
    const float* __restrict__ values,   // [S][B][K]
    const float* __restrict__ w_score,  // [V][2K]
    const float* __restrict__ b_score,  // [V]
    float* __restrict__ out_pred,       // [B][T][V]
    float* __restrict__ out_attn)       // [B][T][S]
{
    const int b = blockIdx.x;
    const int tid = threadIdx.x;
    const int lane = tid & 31;
    const int wid = tid >> 5;            // 16 warps

    __shared__ float sattn[Ss];
    __shared__ float sq[Kk];
    __shared__ float sctx[Kk];
    __shared__ float red[16];

    for (int s = tid; s < Ss; s += 512) sattn[s] = g_energy[b * Ss + s];
    for (int i = tid; i < Kk; i += 512) sq[i] = g_q[(size_t)b * Kk + i];
    __syncthreads();

    // softmax over S
    float m = -3.4e38f;
    for (int s = tid; s < Ss; s += 512) m = fmaxf(m, sattn[s]);
#pragma unroll
    for (int off = 16; off; off >>= 1)
        m = fmaxf(m, __shfl_xor_sync(0xffffffffu, m, off));
    if (lane == 0) red[wid] = m;
    __syncthreads();
    if (wid == 0) {
        float v = (lane < 16) ? red[lane] : -3.4e38f;
#pragma unroll
        for (int off = 8; off; off >>= 1)
            v = fmaxf(v, __shfl_xor_sync(0xffffffffu, v, off));
        if (lane == 0) red[0] = v;
    }
    __syncthreads();
    const float mx = red[0];
    __syncthreads();

    float sum = 0.f;
    for (int s = tid; s < Ss; s += 512) {
        float e = expf(sattn[s] - mx);
        sattn[s] = e;
        sum += e;
    }
#pragma unroll
    for (int off = 16; off; off >>= 1)
        sum += __shfl_xor_sync(0xffffffffu, sum, off);
    if (lane == 0) red[wid] = sum;
    __syncthreads();
    if (wid == 0) {
        float v = (lane < 16) ? red[lane] : 0.f;
#pragma unroll
        for (int off = 8; off; off >>= 1)
            v += __shfl_xor_sync(0xffffffffu, v, off);
        if (lane == 0) red[0] = v;
    }
    __syncthreads();
    const float inv = 1.f / red[0];
    for (int s = tid; s < Ss; s += 512) {
        float a = sattn[s] * inv;
        sattn[s] = a;
        out_attn[((size_t)b * Tt + t) * Ss + s] = a;
    }
    __syncthreads();

    // ctx[k] = sum_s attn[s] * values[s][b][k]  (thread per k, coalesced)
    {
        const size_t base = (size_t)b * Kk + tid;
        const size_t str = (size_t)Bsz * Kk;
        float a0 = 0.f, a1 = 0.f, a2 = 0.f, a3 = 0.f;
        for (int s = 0; s < Ss; s += 4) {
            a0 += sattn[s]     * values[base + (size_t)s * str];
            a1 += sattn[s + 1] * values[base + (size_t)(s + 1) * str];
            a2 += sattn[s + 2] * values[base + (size_t)(s + 2) * str];
            a3 += sattn[s + 3] * values[base + (size_t)(s + 3) * str];
        }
        float r = (a0 + a1) + (a2 + a3);
        sctx[tid] = r;
        g_ctxb[(size_t)b * Kk + tid] = __float2bfloat16_rn(r);  // feeds next-step LSTM
    }
    __syncthreads();

    // score[v] = dot(w_score[v], [q, ctx]) + b_score[v]  (warp per v)
    for (int v = wid; v < Vv; v += 16) {
        const float* wr = w_score + (size_t)v * (2 * Kk);
        float acc = 0.f;
        for (int i = lane; i < Kk; i += 32)
            acc += sq[i] * wr[i] + sctx[i] * wr[Kk + i];
#pragma unroll
        for (int off = 16; off; off >>= 1)
            acc += __shfl_xor_sync(0xffffffffu, acc, off);
        if (lane == 0)
            out_pred[((size_t)b * Tt + t) * Vv + v] = acc + b_score[v];
    }
}

// ---------------- launch ----------------
extern "C" void kernel_launch(void* const* d_in, const int* in_sizes, int n_in,
                              void* d_out, int out_size) {
    const int*   labels  = (const int*)  d_in[0];
    const float* keys    = (const float*)d_in[1];
    const float* values  = (const float*)d_in[2];
    const float* emb     = (const float*)d_in[3];
    const float* w_ih0   = (const float*)d_in[4];
    const float* w_hh0   = (const float*)d_in[5];
    const float* b_ih0   = (const float*)d_in[6];
    const float* b_hh0   = (const float*)d_in[7];
    const float* w_ih1   = (const float*)d_in[8];
    const float* w_hh1   = (const float*)d_in[9];
    const float* b_ih1   = (const float*)d_in[10];
    const float* b_hh1   = (const float*)d_in[11];
    const float* w_ih2   = (const float*)d_in[12];
    const float* w_hh2   = (const float*)d_in[13];
    const float* b_ih2   = (const float*)d_in[14];
    const float* b_hh2   = (const float*)d_in[15];
    const float* w_proj  = (const float*)d_in[16];
    const float* b_proj  = (const float*)d_in[17];
    const float* w_score = (const float*)d_in[18];
    const float* b_score = (const float*)d_in[19];
    const float* h0      = (const float*)d_in[20];

    float* out_pred = (float*)d_out;
    float* out_attn = out_pred + (size_t)Bsz * Tt * Vv;

    cudaFuncSetAttribute(lstm_mma_kernel,
                         cudaFuncAttributeMaxDynamicSharedMemorySize, LSTM_SMEM);

    {
        bf16* wc0;
        cudaGetSymbolAddress((void**)&wc0, g_wcat);
        bf16* wc1 = wc0 + (size_t)4096 * 2048;
        bf16* wc2 = wc1 + (size_t)4096 * 2048;
        convert_w_kernel<<<4096, 256>>>(w_ih0, w_hh0, wc0);
        convert_w_kernel<<<4096, 256>>>(w_ih1, w_hh1, wc1);
        convert_w_kernel<<<4096, 256>>>(w_ih2, w_hh2, wc2);
    }

    embed_kernel<<<Tt * Bsz, 128>>>(labels, emb);
    init_state_kernel<<<(Bsz * Hh + 255) / 256, 256>>>(h0);
    init_ctx_kernel<<<Kk, 256>>>(h0, w_proj, b_proj);

    for (int t = 0; t < Tt; t++) {
        lstm_mma_kernel<<<128, 256, LSTM_SMEM>>>(0, t, b_ih0, b_hh0);
        lstm_mma_kernel<<<128, 256, LSTM_SMEM>>>(1, t, b_ih1, b_hh1);
        lstm_mma_kernel<<<128, 256, LSTM_SMEM>>>(2, t, b_ih2, b_hh2);
        proj_q_kernel<<<128, 256>>>(t, w_proj, b_proj);
        energy_kernel<<<dim3(64, 8), 256>>>(keys);
        attn_fused_kernel<<<64, 512>>>(t, values, w_score, b_score,
                                       out_pred, out_attn);
    }
}

// round 8
// speedup vs baseline: 3.1087x; 1.0337x over previous
#include <cuda_runtime.h>
#include <cuda_bf16.h>
#include <math.h>
#include <stdint.h>
#include <stddef.h>

#define Bsz 64
#define Tt  100
#define Ss  400
#define Ee  512
#define Hh  1024
#define Kk  512
#define Vv  34

typedef __nv_bfloat16 bf16;

// ---------------- static device scratch ----------------
__device__ __align__(256) bf16  g_wcat[3][(size_t)4096 * 2048];  // bf16 weights, concat ih|hh
__device__ __align__(256) bf16  g_xs[(size_t)Tt * Bsz * Ee];     // bf16 embedded inputs
__device__ __align__(256) bf16  g_h1b[2][Bsz * Hh];              // bf16 h states (ping-pong)
__device__ __align__(256) bf16  g_h2b[2][Bsz * Hh];
__device__ __align__(256) bf16  g_h3b[2][Bsz * Hh];
__device__ __align__(256) float g_h3f[2][Bsz * Hh];              // fp32 h3 (for proj)
__device__ __align__(256) float g_c1[Bsz * Hh];
__device__ __align__(256) float g_c2[Bsz * Hh];
__device__ __align__(256) float g_c3[Bsz * Hh];
__device__ __align__(256) bf16  g_ctxb[Bsz * Kk];                // bf16 (gemm)
__device__ __align__(256) float g_q[Bsz * Kk];
__device__ __align__(256) float g_energy[Bsz * Ss];

// ---------------- helpers ----------------
__device__ __forceinline__ void cpa16(uint32_t dst, const void* src) {
    asm volatile("cp.async.ca.shared.global [%0], [%1], 16;\n" :: "r"(dst), "l"(src));
}
#define CPA_COMMIT() asm volatile("cp.async.commit_group;\n" ::: "memory")
#define CPA_WAIT(n)  asm volatile("cp.async.wait_group %0;\n" :: "n"(n) : "memory")

__device__ __forceinline__ void mma_bf16(float* c,
    uint32_t a0, uint32_t a1, uint32_t a2, uint32_t a3,
    uint32_t b0, uint32_t b1) {
    asm volatile(
        "mma.sync.aligned.m16n8k16.row.col.f32.bf16.bf16.f32 "
        "{%0,%1,%2,%3},{%4,%5,%6,%7},{%8,%9},{%0,%1,%2,%3};\n"
        : "+f"(c[0]), "+f"(c[1]), "+f"(c[2]), "+f"(c[3])
        : "r"(a0), "r"(a1), "r"(a2), "r"(a3), "r"(b0), "r"(b1));
}

__device__ __forceinline__ void ldsm4(uint32_t& r0, uint32_t& r1,
                                      uint32_t& r2, uint32_t& r3, uint32_t addr) {
    asm volatile("ldmatrix.sync.aligned.m8n8.x4.shared.b16 {%0,%1,%2,%3}, [%4];"
        : "=r"(r0), "=r"(r1), "=r"(r2), "=r"(r3) : "r"(addr));
}

// ---------------- weight conversion (fp32 -> bf16, concat ih|hh) ----------------
__global__ void convert_w_kernel(const float* __restrict__ w_ih,
                                 const float* __restrict__ w_hh,
                                 bf16* __restrict__ dst) {
    int r = blockIdx.x;                     // 0..4095
    int i = threadIdx.x;                    // 0..255
    float4 va = ((const float4*)(w_ih + (size_t)r * 1024))[i];
    float4 vb = ((const float4*)(w_hh + (size_t)r * 1024))[i];
    __nv_bfloat162* d2 = (__nv_bfloat162*)(dst + (size_t)r * 2048);
    d2[2 * i]           = __floats2bfloat162_rn(va.x, va.y);
    d2[2 * i + 1]       = __floats2bfloat162_rn(va.z, va.w);
    d2[512 + 2 * i]     = __floats2bfloat162_rn(vb.x, vb.y);
    d2[512 + 2 * i + 1] = __floats2bfloat162_rn(vb.z, vb.w);
}

// ---------------- embedding gather (stores bf16) ----------------
__global__ void embed_kernel(const int* __restrict__ labels,
                             const float* __restrict__ emb) {
    int tb = blockIdx.x;
    int t = tb / Bsz;
    int b = tb % Bsz;
    int lab = labels[b * Tt + t];
    const float4* src = (const float4*)(emb + (size_t)lab * Ee);
    __nv_bfloat162* dst = (__nv_bfloat162*)(g_xs + ((size_t)t * Bsz + b) * Ee);
    for (int i = threadIdx.x; i < Ee / 4; i += blockDim.x) {
        float4 v = src[i];
        dst[2 * i]     = __floats2bfloat162_rn(v.x, v.y);
        dst[2 * i + 1] = __floats2bfloat162_rn(v.z, v.w);
    }
}

// ---------------- init h/c ----------------
__global__ void init_state_kernel(const float* __restrict__ h0) {
    int i = blockIdx.x * blockDim.x + threadIdx.x;
    if (i < Bsz * Hh) {
        float v = h0[i % Hh];
        bf16 vb = __float2bfloat16_rn(v);
        g_h1b[0][i] = vb; g_h2b[0][i] = vb; g_h3b[0][i] = vb;
        g_h3f[0][i] = v;
        g_c1[i] = v; g_c2[i] = v; g_c3[i] = v;
    }
}

// ---------------- init ctx0 ----------------
__global__ void init_ctx_kernel(const float* __restrict__ h0,
                                const float* __restrict__ w_proj,
                                const float* __restrict__ b_proj) {
    int k = blockIdx.x;
    __shared__ float red[256];
    float s = 0.f;
    for (int i = threadIdx.x; i < Hh; i += 256)
        s += h0[i] * w_proj[(size_t)k * Hh + i];
    red[threadIdx.x] = s;
    __syncthreads();
    for (int off = 128; off; off >>= 1) {
        if (threadIdx.x < off) red[threadIdx.x] += red[threadIdx.x + off];
        __syncthreads();
    }
    float v = red[0] + b_proj[k];
    if (threadIdx.x < Bsz)
        g_ctxb[(size_t)threadIdx.x * Kk + k] = __float2bfloat16_rn(v);
}

// ---------------- bf16 MMA LSTM cell ----------------
// C[64 x 4096] = A[64 x 2048] @ Wcat^T ; block owns 8 j x 4 gates (N=32 cols),
// grid = 128 blocks, 256 threads (8 warps: 4 m-tiles x 2 n-halves).
// 7-stage cp.async pipeline, prefetch distance 5, ldmatrix fragment loads,
// single __syncthreads per iteration (STAGES >= PFD+2 makes trailing sync redundant).
#define BK 64
#define STAGES 7
#define PFD 5
#define APAD 72                      // bf16 elements per row (64 + 8 pad)
#define A_ST (64 * APAD)             // bf16 elements
#define B_ST (32 * APAD)
#define STAGE_ELE (A_ST + B_ST)      // 6912 bf16 = 13824 B
#define LSTM_SMEM (STAGES * STAGE_ELE * 2)

struct SegInfo { const bf16* p; int stride; };

__device__ __forceinline__ SegInfo a_seg(int cell, int p, int t, int seg) {
    SegInfo r;
    if (cell == 0) {
        if (seg == 0)      { r.p = g_xs + (size_t)t * Bsz * Ee; r.stride = Ee; }
        else if (seg == 1) { r.p = g_ctxb;                      r.stride = Kk; }
        else               { r.p = g_h1b[p] + (seg - 2) * 512;  r.stride = Hh; }
    } else if (cell == 1) {
        if (seg < 2) { r.p = g_h1b[1 - p] + seg * 512;       r.stride = Hh; }
        else         { r.p = g_h2b[p]     + (seg - 2) * 512; r.stride = Hh; }
    } else {
        if (seg < 2) { r.p = g_h2b[1 - p] + seg * 512;       r.stride = Hh; }
        else         { r.p = g_h3b[p]     + (seg - 2) * 512; r.stride = Hh; }
    }
    return r;
}

__global__ void __launch_bounds__(256) lstm_mma_kernel(
    int cell, int t,
    const float* __restrict__ b_ih, const float* __restrict__ b_hh)
{
    extern __shared__ __align__(16) char smem_raw[];
    bf16* smem = (bf16*)smem_raw;
    const int p = t & 1;
    const int tid = threadIdx.x;
    const int lane = tid & 31;
    const int warp = tid >> 5;
    const int wm = warp & 3;
    const int wn = warp >> 2;
    const int j0 = blockIdx.x * 8;
    const bf16* __restrict__ wcat = g_wcat[cell];

    float* c_st; bf16* h_ob; float* h_f;
    if (cell == 0)      { c_st = g_c1; h_ob = g_h1b[1 - p]; h_f = nullptr; }
    else if (cell == 1) { c_st = g_c2; h_ob = g_h2b[1 - p]; h_f = nullptr; }
    else                { c_st = g_c3; h_ob = g_h3b[1 - p]; h_f = g_h3f[1 - p]; }

    const uint32_t smem_u = (uint32_t)__cvta_generic_to_shared(smem);

    float acc0[4] = {0.f, 0.f, 0.f, 0.f};
    float acc1[4] = {0.f, 0.f, 0.f, 0.f};

    const int NTILES = 2048 / BK;   // 32

    auto issue_tile = [&](int kt, int ss) {
        const int k0 = kt * BK;
        SegInfo si = a_seg(cell, p, t, k0 >> 9);
        const int kin = k0 & 511;
        const uint32_t abase = smem_u + (uint32_t)(ss * STAGE_ELE) * 2u;
        const uint32_t bbase = abase + (uint32_t)A_ST * 2u;
#pragma unroll
        for (int j = 0; j < 2; j++) {            // A: 512 chunks of 8 bf16
            int i = tid + j * 256;
            int m = i >> 3, c8 = i & 7;
            const bf16* src = si.p + (size_t)m * si.stride + kin + c8 * 8;
            cpa16(abase + (uint32_t)(m * APAD + c8 * 8) * 2u, src);
        }
        {                                        // B: 256 chunks of 8 bf16
            int n = tid >> 3, c8 = tid & 7;
            int r = (n >> 3) * 1024 + j0 + (n & 7);
            const bf16* src = wcat + (size_t)r * 2048 + k0 + c8 * 8;
            cpa16(bbase + (uint32_t)(n * APAD + c8 * 8) * 2u, src);
        }
    };

    // prologue: prefetch PFD tiles
#pragma unroll
    for (int i = 0; i < PFD; i++) { issue_tile(i, i); CPA_COMMIT(); }

    // ldmatrix lane->address maps (element offsets within stage):
    // A: row = wm*16 + (lane&15), col = (lane>>4)*8      (+kb per ks)
    // B: row = wn*16 + ((lane>>4)<<3) + (lane&7), col = ((lane>>3)&1)*8
    const uint32_t a_lane_off =
        (uint32_t)((wm * 16 + (lane & 15)) * APAD + (lane >> 4) * 8) * 2u;
    const uint32_t b_lane_off =
        (uint32_t)((wn * 16 + ((lane >> 4) << 3) + (lane & 7)) * APAD
                   + ((lane >> 3) & 1) * 8) * 2u;

    for (int kt = 0; kt < NTILES; kt++) {
        if (kt + PFD < NTILES) issue_tile(kt + PFD, (kt + PFD) % STAGES);
        CPA_COMMIT();
        CPA_WAIT(PFD);
        __syncthreads();

        const uint32_t As_u = smem_u + (uint32_t)((kt % STAGES) * STAGE_ELE) * 2u;
        const uint32_t Bs_u = As_u + (uint32_t)A_ST * 2u;
#pragma unroll
        for (int ks = 0; ks < BK / 16; ks++) {
            const uint32_t kb2 = (uint32_t)(ks * 16) * 2u;
            uint32_t a0, a1, a2, a3, b0, b1, b2, b3;
            ldsm4(a0, a1, a2, a3, As_u + a_lane_off + kb2);
            ldsm4(b0, b1, b2, b3, Bs_u + b_lane_off + kb2);
            mma_bf16(acc0, a0, a1, a2, a3, b0, b1);
            mma_bf16(acc1, a0, a1, a2, a3, b2, b3);
        }
        // no trailing sync: stage reuse distance (STAGES-PFD)=2 is covered by
        // the leading __syncthreads of the next iteration.
    }
    CPA_WAIT(0);
    __syncthreads();

    // ---- stage C through smem: Cs[64][33] floats, col n = g*8 + jj ----
    float* Cs = (float*)smem_raw;
    {
        const int ar = lane >> 2;
        const int ac = lane & 3;
        int crow = wm * 16 + ar;
        int cc0 = wn * 16 + 2 * ac;
        Cs[crow * 33 + cc0]           = acc0[0];
        Cs[crow * 33 + cc0 + 1]       = acc0[1];
        Cs[(crow + 8) * 33 + cc0]     = acc0[2];
        Cs[(crow + 8) * 33 + cc0 + 1] = acc0[3];
        Cs[crow * 33 + cc0 + 8]       = acc1[0];
        Cs[crow * 33 + cc0 + 9]       = acc1[1];
        Cs[(crow + 8) * 33 + cc0 + 8] = acc1[2];
        Cs[(crow + 8) * 33 + cc0 + 9] = acc1[3];
    }
    __syncthreads();

    // ---- fused LSTM update: 512 (m, jj) pairs, 2 per thread ----
#pragma unroll
    for (int j = 0; j < 2; j++) {
        int pr = tid + j * 256;
        int m = pr & 63;
        int jj = pr >> 6;
        int jg = j0 + jj;
        float gi = Cs[m * 33 + jj]      + b_ih[jg]        + b_hh[jg];
        float gf = Cs[m * 33 + 8 + jj]  + b_ih[1024 + jg] + b_hh[1024 + jg];
        float gg = Cs[m * 33 + 16 + jj] + b_ih[2048 + jg] + b_hh[2048 + jg];
        float go = Cs[m * 33 + 24 + jj] + b_ih[3072 + jg] + b_hh[3072 + jg];
        float si = 1.f / (1.f + expf(-gi));
        float sf = 1.f / (1.f + expf(-gf));
        float so = 1.f / (1.f + expf(-go));
        float cn = sf * c_st[(size_t)m * Hh + jg] + si * tanhf(gg);
        c_st[(size_t)m * Hh + jg] = cn;
        float hn = so * tanhf(cn);
        h_ob[(size_t)m * Hh + jg] = __float2bfloat16_rn(hn);
        if (h_f) h_f[(size_t)m * Hh + jg] = hn;
    }
}

// ---------------- q = h3 @ w_proj^T + b_proj (smem-tiled, 128 blocks) ----------------
__global__ void __launch_bounds__(256) proj_q_kernel(
    int t, const float* __restrict__ w_proj, const float* __restrict__ b_proj)
{
    __shared__ float sw[4 * 1024];
    const int tid = threadIdx.x;
    const int kb = blockIdx.x;           // 0..127, 4 k's each
    const float4* wp4 = (const float4*)(w_proj + (size_t)kb * 4 * 1024);
    float4* sw4 = (float4*)sw;
#pragma unroll
    for (int j = 0; j < 4; j++) sw4[tid + j * 256] = wp4[tid + j * 256];
    __syncthreads();

    const float* h3 = g_h3f[1 - (t & 1)];
    int b = tid >> 2;
    int kl = tid & 3;
    const float4* hr = (const float4*)(h3 + (size_t)b * Hh);
    const float4* w0 = (const float4*)(sw + kl * 1024);
    float a0 = 0.f, a1 = 0.f;
#pragma unroll 4
    for (int i = 0; i < 256; i += 2) {
        float4 h4 = hr[i];
        float4 x0 = w0[i];
        a0 += h4.x * x0.x + h4.y * x0.y + h4.z * x0.z + h4.w * x0.w;
        float4 h5 = hr[i + 1];
        float4 x1 = w0[i + 1];
        a1 += h5.x * x1.x + h5.y * x1.y + h5.z * x1.z + h5.w * x1.w;
    }
    int kg = kb * 4 + kl;
    g_q[(size_t)b * Kk + kg] = a0 + a1 + b_proj[kg];
}

// ---------------- energy: grid (64 b, 8 s-chunks), 256 threads ----------------
__global__ void __launch_bounds__(256) energy_kernel(const float* __restrict__ keys) {
    const int b = blockIdx.x;
    const int sc = blockIdx.y;
    const int tid = threadIdx.x;
    const int lane = tid & 31;
    const int wid = tid >> 5;
    __shared__ float sq[Kk];
    if (tid < 128)
        ((float4*)sq)[tid] = ((const float4*)(g_q + (size_t)b * Kk))[tid];
    __syncthreads();
    const float4* qr = (const float4*)sq;
    for (int s = sc * 50 + wid; s < sc * 50 + 50; s += 8) {
        const float4* kr = (const float4*)(keys + ((size_t)s * Bsz + b) * Kk);
        float acc = 0.f;
#pragma unroll
        for (int i = 0; i < 4; i++) {
            float4 k4 = kr[lane + i * 32];
            float4 q4 = qr[lane + i * 32];
            acc += k4.x * q4.x + k4.y * q4.y + k4.z * q4.z + k4.w * q4.w;
        }
#pragma unroll
        for (int off = 16; off; off >>= 1)
            acc += __shfl_xor_sync(0xffffffffu, acc, off);
        if (lane == 0) g_energy[b * Ss + s] = acc;
    }
}

// ---------------- fused softmax + ctx + score: grid 64, 512 threads ----------------
__global__ void __launch_bounds__(512) attn_fused_kernel(
    int t,
    const float* __restrict__ values,   // [S][B][K]
    const float* __restrict__ w_score,  // [V][2K]
    const float* __restrict__ b_score,  // [V]
    float* __restrict__ out_pred,       // [B][T][V]
    float* __restrict__ out_attn)       // [B][T][S]
{
    const int b = blockIdx.x;
    const int tid = threadIdx.x;
    const int lane = tid & 31;
    const int wid = tid >> 5;            // 16 warps

    __shared__ float sattn[Ss];
    __shared__ float sq[Kk];
    __shared__ float sctx[Kk];
    __shared__ float red[16];

    for (int s = tid; s < Ss; s += 512) sattn[s] = g_energy[b * Ss + s];
    for (int i = tid; i < Kk; i += 512) sq[i] = g_q[(size_t)b * Kk + i];
    __syncthreads();

    // softmax over S
    float m = -3.4e38f;
    for (int s = tid; s < Ss; s += 512) m = fmaxf(m, sattn[s]);
#pragma unroll
    for (int off = 16; off; off >>= 1)
        m = fmaxf(m, __shfl_xor_sync(0xffffffffu, m, off));
    if (lane == 0) red[wid] = m;
    __syncthreads();
    if (wid == 0) {
        float v = (lane < 16) ? red[lane] : -3.4e38f;
#pragma unroll
        for (int off = 8; off; off >>= 1)
            v = fmaxf(v, __shfl_xor_sync(0xffffffffu, v, off));
        if (lane == 0) red[0] = v;
    }
    __syncthreads();
    const float mx = red[0];
    __syncthreads();

    float sum = 0.f;
    for (int s = tid; s < Ss; s += 512) {
        float e = expf(sattn[s] - mx);
        sattn[s] = e;
        sum += e;
    }
#pragma unroll
    for (int off = 16; off; off >>= 1)
        sum += __shfl_xor_sync(0xffffffffu, sum, off);
    if (lane == 0) red[wid] = sum;
    __syncthreads();
    if (wid == 0) {
        float v = (lane < 16) ? red[lane] : 0.f;
#pragma unroll
        for (int off = 8; off; off >>= 1)
            v += __shfl_xor_sync(0xffffffffu, v, off);
        if (lane == 0) red[0] = v;
    }
    __syncthreads();
    const float inv = 1.f / red[0];
    for (int s = tid; s < Ss; s += 512) {
        float a = sattn[s] * inv;
        sattn[s] = a;
        out_attn[((size_t)b * Tt + t) * Ss + s] = a;
    }
    __syncthreads();

    // ctx[k] = sum_s attn[s] * values[s][b][k]  (thread per k, coalesced)
    {
        const size_t base = (size_t)b * Kk + tid;
        const size_t str = (size_t)Bsz * Kk;
        float a0 = 0.f, a1 = 0.f, a2 = 0.f, a3 = 0.f;
        for (int s = 0; s < Ss; s += 4) {
            a0 += sattn[s]     * values[base + (size_t)s * str];
            a1 += sattn[s + 1] * values[base + (size_t)(s + 1) * str];
            a2 += sattn[s + 2] * values[base + (size_t)(s + 2) * str];
            a3 += sattn[s + 3] * values[base + (size_t)(s + 3) * str];
        }
        float r = (a0 + a1) + (a2 + a3);
        sctx[tid] = r;
        g_ctxb[(size_t)b * Kk + tid] = __float2bfloat16_rn(r);  // feeds next-step LSTM
    }
    __syncthreads();

    // score[v] = dot(w_score[v], [q, ctx]) + b_score[v]  (warp per v)
    for (int v = wid; v < Vv; v += 16) {
        const float* wr = w_score + (size_t)v * (2 * Kk);
        float acc = 0.f;
        for (int i = lane; i < Kk; i += 32)
            acc += sq[i] * wr[i] + sctx[i] * wr[Kk + i];
#pragma unroll
        for (int off = 16; off; off >>= 1)
            acc += __shfl_xor_sync(0xffffffffu, acc, off);
        if (lane == 0)
            out_pred[((size_t)b * Tt + t) * Vv + v] = acc + b_score[v];
    }
}

// ---------------- launch ----------------
extern "C" void kernel_launch(void* const* d_in, const int* in_sizes, int n_in,
                              void* d_out, int out_size) {
    const int*   labels  = (const int*)  d_in[0];
    const float* keys    = (const float*)d_in[1];
    const float* values  = (const float*)d_in[2];
    const float* emb     = (const float*)d_in[3];
    const float* w_ih0   = (const float*)d_in[4];
    const float* w_hh0   = (const float*)d_in[5];
    const float* b_ih0   = (const float*)d_in[6];
    const float* b_hh0   = (const float*)d_in[7];
    const float* w_ih1   = (const float*)d_in[8];
    const float* w_hh1   = (const float*)d_in[9];
    const float* b_ih1   = (const float*)d_in[10];
    const float* b_hh1   = (const float*)d_in[11];
    const float* w_ih2   = (const float*)d_in[12];
    const float* w_hh2   = (const float*)d_in[13];
    const float* b_ih2   = (const float*)d_in[14];
    const float* b_hh2   = (const float*)d_in[15];
    const float* w_proj  = (const float*)d_in[16];
    const float* b_proj  = (const float*)d_in[17];
    const float* w_score = (const float*)d_in[18];
    const float* b_score = (const float*)d_in[19];
    const float* h0      = (const float*)d_in[20];

    float* out_pred = (float*)d_out;
    float* out_attn = out_pred + (size_t)Bsz * Tt * Vv;

    cudaFuncSetAttribute(lstm_mma_kernel,
                         cudaFuncAttributeMaxDynamicSharedMemorySize, LSTM_SMEM);

    {
        bf16* wc0;
        cudaGetSymbolAddress((void**)&wc0, g_wcat);
        bf16* wc1 = wc0 + (size_t)4096 * 2048;
        bf16* wc2 = wc1 + (size_t)4096 * 2048;
        convert_w_kernel<<<4096, 256>>>(w_ih0, w_hh0, wc0);
        convert_w_kernel<<<4096, 256>>>(w_ih1, w_hh1, wc1);
        convert_w_kernel<<<4096, 256>>>(w_ih2, w_hh2, wc2);
    }

    embed_kernel<<<Tt * Bsz, 128>>>(labels, emb);
    init_state_kernel<<<(Bsz * Hh + 255) / 256, 256>>>(h0);
    init_ctx_kernel<<<Kk, 256>>>(h0, w_proj, b_proj);

    for (int t = 0; t < Tt; t++) {
        lstm_mma_kernel<<<128, 256, LSTM_SMEM>>>(0, t, b_ih0, b_hh0);
        lstm_mma_kernel<<<128, 256, LSTM_SMEM>>>(1, t, b_ih1, b_hh1);
        lstm_mma_kernel<<<128, 256, LSTM_SMEM>>>(2, t, b_ih2, b_hh2);
        proj_q_kernel<<<128, 256>>>(t, w_proj, b_proj);
        energy_kernel<<<dim3(64, 8), 256>>>(keys);
        attn_fused_kernel<<<64, 512>>>(t, values, w_score, b_score,
                                       out_pred, out_attn);
    }
}

// round 9
// speedup vs baseline: 3.6300x; 1.1677x over previous
#include <cuda_runtime.h>
#include <cuda_bf16.h>
#include <math.h>
#include <stdint.h>
#include <stddef.h>

#define Bsz 64
#define Tt  100
#define Ss  400
#define Ee  512
#define Hh  1024
#define Kk  512
#define Vv  34

#define NCTA 128

typedef __nv_bfloat16 bf16;

// ---------------- static device scratch ----------------
__device__ __align__(256) bf16  g_wcat[3][(size_t)4096 * 2048];  // bf16 weights, concat ih|hh
__device__ __align__(256) bf16  g_xs[(size_t)Tt * Bsz * Ee];     // bf16 embedded inputs
__device__ __align__(256) bf16  g_h1b[2][Bsz * Hh];              // bf16 h states (ping-pong)
__device__ __align__(256) bf16  g_h2b[2][Bsz * Hh];
__device__ __align__(256) bf16  g_h3b[2][Bsz * Hh];
__device__ __align__(256) float g_h3f[2][Bsz * Hh];              // fp32 h3 (for proj)
__device__ __align__(256) float g_c1[Bsz * Hh];
__device__ __align__(256) float g_c2[Bsz * Hh];
__device__ __align__(256) float g_c3[Bsz * Hh];
__device__ __align__(256) bf16  g_ctxb[Bsz * Kk];                // bf16 (gemm input)
__device__ __align__(256) float g_q[Bsz * Kk];
__device__ __align__(256) float g_energy[Bsz * Ss];

// grid barrier state (monotonic epoch; survives replays correctly)
__device__ unsigned g_cnt = 0;
__device__ unsigned g_epoch = 0;

// ---------------- helpers ----------------
__device__ __forceinline__ void cpa16(uint32_t dst, const void* src) {
    asm volatile("cp.async.ca.shared.global [%0], [%1], 16;\n" :: "r"(dst), "l"(src));
}
#define CPA_COMMIT() asm volatile("cp.async.commit_group;\n" ::: "memory")
#define CPA_WAIT(n)  asm volatile("cp.async.wait_group %0;\n" :: "n"(n) : "memory")

__device__ __forceinline__ void mma_bf16(float* c,
    uint32_t a0, uint32_t a1, uint32_t a2, uint32_t a3,
    uint32_t b0, uint32_t b1) {
    asm volatile(
        "mma.sync.aligned.m16n8k16.row.col.f32.bf16.bf16.f32 "
        "{%0,%1,%2,%3},{%4,%5,%6,%7},{%8,%9},{%0,%1,%2,%3};\n"
        : "+f"(c[0]), "+f"(c[1]), "+f"(c[2]), "+f"(c[3])
        : "r"(a0), "r"(a1), "r"(a2), "r"(a3), "r"(b0), "r"(b1));
}

__device__ __forceinline__ void ldsm4(uint32_t& r0, uint32_t& r1,
                                      uint32_t& r2, uint32_t& r3, uint32_t addr) {
    asm volatile("ldmatrix.sync.aligned.m8n8.x4.shared.b16 {%0,%1,%2,%3}, [%4];"
        : "=r"(r0), "=r"(r1), "=r"(r2), "=r"(r3) : "r"(addr));
}

// grid-wide barrier: release (threadfence) + counting arrive + epoch spin + acquire.
__device__ __forceinline__ void grid_bar(unsigned target) {
    __threadfence();           // release this thread's writes (device scope)
    __syncthreads();
    if (threadIdx.x == 0) {
        unsigned n = atomicAdd(&g_cnt, 1u);
        if (n == NCTA - 1u) {
            g_cnt = 0;
            __threadfence();
            atomicAdd(&g_epoch, 1u);
        } else {
            while (*(volatile unsigned*)&g_epoch < target) __nanosleep(64);
        }
        __threadfence();       // acquire: CCTL.IVALL invalidates this SM's L1D
    }
    __syncthreads();
}

// ---------------- LSTM tiling constants ----------------
#define BK 64
#define STAGES 7
#define PFD 5
#define APAD 72
#define A_ST (64 * APAD)
#define B_ST (32 * APAD)
#define STAGE_ELE (A_ST + B_ST)
#define LSTM_SMEM (STAGES * STAGE_ELE * 2)

struct SegInfo { const bf16* p; int stride; };

__device__ __forceinline__ SegInfo a_seg(int cell, int p, int t, int seg) {
    SegInfo r;
    if (cell == 0) {
        if (seg == 0)      { r.p = g_xs + (size_t)t * Bsz * Ee; r.stride = Ee; }
        else if (seg == 1) { r.p = g_ctxb;                      r.stride = Kk; }
        else               { r.p = g_h1b[p] + (seg - 2) * 512;  r.stride = Hh; }
    } else if (cell == 1) {
        if (seg < 2) { r.p = g_h1b[1 - p] + seg * 512;       r.stride = Hh; }
        else         { r.p = g_h2b[p]     + (seg - 2) * 512; r.stride = Hh; }
    } else {
        if (seg < 2) { r.p = g_h2b[1 - p] + seg * 512;       r.stride = Hh; }
        else         { r.p = g_h3b[p]     + (seg - 2) * 512; r.stride = Hh; }
    }
    return r;
}

// ---------------- lstm phase (runs on all 128 CTAs) ----------------
__device__ __forceinline__ void lstm_phase(
    char* smem_raw, int cell, int t,
    const float* __restrict__ b_ih, const float* __restrict__ b_hh)
{
    bf16* smem = (bf16*)smem_raw;
    const int p = t & 1;
    const int tid = threadIdx.x;
    const int lane = tid & 31;
    const int warp = tid >> 5;
    const int wm = warp & 3;
    const int wn = warp >> 2;
    const int j0 = blockIdx.x * 8;
    const bf16* __restrict__ wcat = g_wcat[cell];

    float* c_st; bf16* h_ob; float* h_f;
    if (cell == 0)      { c_st = g_c1; h_ob = g_h1b[1 - p]; h_f = nullptr; }
    else if (cell == 1) { c_st = g_c2; h_ob = g_h2b[1 - p]; h_f = nullptr; }
    else                { c_st = g_c3; h_ob = g_h3b[1 - p]; h_f = g_h3f[1 - p]; }

    const uint32_t smem_u = (uint32_t)__cvta_generic_to_shared(smem);

    float acc0[4] = {0.f, 0.f, 0.f, 0.f};
    float acc1[4] = {0.f, 0.f, 0.f, 0.f};

    const int NTILES = 2048 / BK;

    auto issue_tile = [&](int kt, int ss) {
        const int k0 = kt * BK;
        SegInfo si = a_seg(cell, p, t, k0 >> 9);
        const int kin = k0 & 511;
        const uint32_t abase = smem_u + (uint32_t)(ss * STAGE_ELE) * 2u;
        const uint32_t bbase = abase + (uint32_t)A_ST * 2u;
#pragma unroll
        for (int j = 0; j < 2; j++) {
            int i = tid + j * 256;
            int m = i >> 3, c8 = i & 7;
            const bf16* src = si.p + (size_t)m * si.stride + kin + c8 * 8;
            cpa16(abase + (uint32_t)(m * APAD + c8 * 8) * 2u, src);
        }
        {
            int n = tid >> 3, c8 = tid & 7;
            int r = (n >> 3) * 1024 + j0 + (n & 7);
            const bf16* src = wcat + (size_t)r * 2048 + k0 + c8 * 8;
            cpa16(bbase + (uint32_t)(n * APAD + c8 * 8) * 2u, src);
        }
    };

#pragma unroll
    for (int i = 0; i < PFD; i++) { issue_tile(i, i); CPA_COMMIT(); }

    const uint32_t a_lane_off =
        (uint32_t)((wm * 16 + (lane & 15)) * APAD + (lane >> 4) * 8) * 2u;
    const uint32_t b_lane_off =
        (uint32_t)((wn * 16 + ((lane >> 4) << 3) + (lane & 7)) * APAD
                   + ((lane >> 3) & 1) * 8) * 2u;

    for (int kt = 0; kt < NTILES; kt++) {
        if (kt + PFD < NTILES) issue_tile(kt + PFD, (kt + PFD) % STAGES);
        CPA_COMMIT();
        CPA_WAIT(PFD);
        __syncthreads();

        const uint32_t As_u = smem_u + (uint32_t)((kt % STAGES) * STAGE_ELE) * 2u;
        const uint32_t Bs_u = As_u + (uint32_t)A_ST * 2u;
#pragma unroll
        for (int ks = 0; ks < BK / 16; ks++) {
            const uint32_t kb2 = (uint32_t)(ks * 16) * 2u;
            uint32_t a0, a1, a2, a3, b0, b1, b2, b3;
            ldsm4(a0, a1, a2, a3, As_u + a_lane_off + kb2);
            ldsm4(b0, b1, b2, b3, Bs_u + b_lane_off + kb2);
            mma_bf16(acc0, a0, a1, a2, a3, b0, b1);
            mma_bf16(acc1, a0, a1, a2, a3, b2, b3);
        }
    }
    CPA_WAIT(0);
    __syncthreads();

    float* Cs = (float*)smem_raw;
    {
        const int ar = lane >> 2;
        const int ac = lane & 3;
        int crow = wm * 16 + ar;
        int cc0 = wn * 16 + 2 * ac;
        Cs[crow * 33 + cc0]           = acc0[0];
        Cs[crow * 33 + cc0 + 1]       = acc0[1];
        Cs[(crow + 8) * 33 + cc0]     = acc0[2];
        Cs[(crow + 8) * 33 + cc0 + 1] = acc0[3];
        Cs[crow * 33 + cc0 + 8]       = acc1[0];
        Cs[crow * 33 + cc0 + 9]       = acc1[1];
        Cs[(crow + 8) * 33 + cc0 + 8] = acc1[2];
        Cs[(crow + 8) * 33 + cc0 + 9] = acc1[3];
    }
    __syncthreads();

#pragma unroll
    for (int j = 0; j < 2; j++) {
        int pr = tid + j * 256;
        int m = pr & 63;
        int jj = pr >> 6;
        int jg = j0 + jj;
        float gi = Cs[m * 33 + jj]      + b_ih[jg]        + b_hh[jg];
        float gf = Cs[m * 33 + 8 + jj]  + b_ih[1024 + jg] + b_hh[1024 + jg];
        float gg = Cs[m * 33 + 16 + jj] + b_ih[2048 + jg] + b_hh[2048 + jg];
        float go = Cs[m * 33 + 24 + jj] + b_ih[3072 + jg] + b_hh[3072 + jg];
        float si = 1.f / (1.f + expf(-gi));
        float sf = 1.f / (1.f + expf(-gf));
        float so = 1.f / (1.f + expf(-go));
        float cn = sf * c_st[(size_t)m * Hh + jg] + si * tanhf(gg);
        c_st[(size_t)m * Hh + jg] = cn;
        float hn = so * tanhf(cn);
        h_ob[(size_t)m * Hh + jg] = __float2bfloat16_rn(hn);
        if (h_f) h_f[(size_t)m * Hh + jg] = hn;
    }
}

// ---------------- the single persistent decoder kernel ----------------
__global__ void __launch_bounds__(256, 1) decoder_kernel(
    const int* __restrict__ labels, const float* __restrict__ keys,
    const float* __restrict__ values, const float* __restrict__ emb,
    const float* __restrict__ w_ih0, const float* __restrict__ w_hh0,
    const float* __restrict__ b_ih0, const float* __restrict__ b_hh0,
    const float* __restrict__ w_ih1, const float* __restrict__ w_hh1,
    const float* __restrict__ b_ih1, const float* __restrict__ b_hh1,
    const float* __restrict__ w_ih2, const float* __restrict__ w_hh2,
    const float* __restrict__ b_ih2, const float* __restrict__ b_hh2,
    const float* __restrict__ w_proj, const float* __restrict__ b_proj,
    const float* __restrict__ w_score, const float* __restrict__ b_score,
    const float* __restrict__ h0,
    float* __restrict__ out_pred, float* __restrict__ out_attn)
{
    extern __shared__ __align__(16) char smem_raw[];
    const int tid = threadIdx.x;
    const int cta = blockIdx.x;
    const int lane = tid & 31;
    const int wid = tid >> 5;

    // entry epoch (all CTAs read the same value: no increment can occur
    // before all 128 have arrived at barrier #1)
    const unsigned ep0 = *(volatile unsigned*)&g_epoch;
    unsigned nbar = 0;

    // ================= PREP =================
    {
        const float* wih[3] = {w_ih0, w_ih1, w_ih2};
        const float* whh[3] = {w_hh0, w_hh1, w_hh2};
        for (int r = cta; r < 3 * 4096; r += NCTA) {
            int cell = r >> 12, row = r & 4095;
            float4 va = ((const float4*)(wih[cell] + (size_t)row * 1024))[tid];
            float4 vb = ((const float4*)(whh[cell] + (size_t)row * 1024))[tid];
            __nv_bfloat162* d2 = (__nv_bfloat162*)(g_wcat[cell] + (size_t)row * 2048);
            d2[2 * tid]           = __floats2bfloat162_rn(va.x, va.y);
            d2[2 * tid + 1]       = __floats2bfloat162_rn(va.z, va.w);
            d2[512 + 2 * tid]     = __floats2bfloat162_rn(vb.x, vb.y);
            d2[512 + 2 * tid + 1] = __floats2bfloat162_rn(vb.z, vb.w);
        }
        // embedding
        for (int tb = cta; tb < Tt * Bsz; tb += NCTA) {
            int t = tb / Bsz, b = tb % Bsz;
            int lab = labels[b * Tt + t];
            if (tid < 128) {
                float4 v = ((const float4*)(emb + (size_t)lab * Ee))[tid];
                __nv_bfloat162* dst =
                    (__nv_bfloat162*)(g_xs + ((size_t)t * Bsz + b) * Ee);
                dst[2 * tid]     = __floats2bfloat162_rn(v.x, v.y);
                dst[2 * tid + 1] = __floats2bfloat162_rn(v.z, v.w);
            }
        }
        // init h/c
#pragma unroll
        for (int j = 0; j < 2; j++) {
            int i = cta * 512 + j * 256 + tid;
            float v = h0[i & (Hh - 1)];
            bf16 vb = __float2bfloat16_rn(v);
            g_h1b[0][i] = vb; g_h2b[0][i] = vb; g_h3b[0][i] = vb;
            g_h3f[0][i] = v;
            g_c1[i] = v; g_c2[i] = v; g_c3[i] = v;
        }
        // zero out_pred (atomicAdd target)
        for (int i = cta * 256 + tid; i < Bsz * Tt * Vv; i += NCTA * 256)
            out_pred[i] = 0.f;
        // ctx0
        float* red = (float*)smem_raw;
        for (int kk = 0; kk < 4; kk++) {
            int k = cta * 4 + kk;
            float s = 0.f;
            for (int i = tid; i < Hh; i += 256)
                s += h0[i] * w_proj[(size_t)k * Hh + i];
#pragma unroll
            for (int off = 16; off; off >>= 1)
                s += __shfl_xor_sync(0xffffffffu, s, off);
            if (lane == 0) red[wid] = s;
            __syncthreads();
            if (tid == 0) {
                float v = 0.f;
#pragma unroll
                for (int j = 0; j < 8; j++) v += red[j];
                red[8] = v + b_proj[k];
            }
            __syncthreads();
            float v = red[8];
            if (tid < Bsz) g_ctxb[(size_t)tid * Kk + k] = __float2bfloat16_rn(v);
            __syncthreads();
        }
    }
    grid_bar(ep0 + ++nbar);

    // ================= TIME LOOP =================
    for (int t = 0; t < Tt; t++) {
        lstm_phase(smem_raw, 0, t, b_ih0, b_hh0);
        grid_bar(ep0 + ++nbar);
        lstm_phase(smem_raw, 1, t, b_ih1, b_hh1);
        grid_bar(ep0 + ++nbar);
        lstm_phase(smem_raw, 2, t, b_ih2, b_hh2);
        grid_bar(ep0 + ++nbar);

        // ---- proj: q = h3 @ w_proj^T + b_proj (kb = cta, 4 k's) ----
        {
            float* sw = (float*)smem_raw;  // 4*1024 floats = 16 KB
            const float4* wp4 = (const float4*)(w_proj + (size_t)cta * 4 * 1024);
            float4* sw4 = (float4*)sw;
#pragma unroll
            for (int j = 0; j < 4; j++) sw4[tid + j * 256] = wp4[tid + j * 256];
            __syncthreads();

            const float* h3 = g_h3f[1 - (t & 1)];
            int b = tid >> 2;
            int kl = tid & 3;
            const float4* hr = (const float4*)(h3 + (size_t)b * Hh);
            const float4* w0 = (const float4*)(sw + kl * 1024);
            float a0 = 0.f, a1 = 0.f;
#pragma unroll 4
            for (int i = 0; i < 256; i += 2) {
                float4 h4 = hr[i];
                float4 x0 = w0[i];
                a0 += h4.x * x0.x + h4.y * x0.y + h4.z * x0.z + h4.w * x0.w;
                float4 h5 = hr[i + 1];
                float4 x1 = w0[i + 1];
                a1 += h5.x * x1.x + h5.y * x1.y + h5.z * x1.z + h5.w * x1.w;
            }
            int kg = cta * 4 + kl;
            g_q[(size_t)b * Kk + kg] = a0 + a1 + b_proj[kg];
        }
        grid_bar(ep0 + ++nbar);

        // ---- energy: cta -> (b = cta&63, half = cta>>6), 200 s each ----
        {
            float* sq = (float*)smem_raw;
            const int b = cta & 63;
            const int half = cta >> 6;
            if (tid < 128)
                ((float4*)sq)[tid] = ((const float4*)(g_q + (size_t)b * Kk))[tid];
            __syncthreads();
            const float4* qr = (const float4*)sq;
            for (int s = half * 200 + wid; s < half * 200 + 200; s += 8) {
                const float4* kr = (const float4*)(keys + ((size_t)s * Bsz + b) * Kk);
                float acc = 0.f;
#pragma unroll
                for (int i = 0; i < 4; i++) {
                    float4 k4 = kr[lane + i * 32];
                    float4 q4 = qr[lane + i * 32];
                    acc += k4.x * q4.x + k4.y * q4.y + k4.z * q4.z + k4.w * q4.w;
                }
#pragma unroll
                for (int off = 16; off; off >>= 1)
                    acc += __shfl_xor_sync(0xffffffffu, acc, off);
                if (lane == 0) g_energy[b * Ss + s] = acc;
            }
            __syncthreads();
        }
        grid_bar(ep0 + ++nbar);

        // ---- softmax + ctx + partial score (cta -> b, half k-range) ----
        {
            float* sattn = (float*)smem_raw;          // 400
            float* sctx  = sattn + Ss;                 // 256
            float* sqh   = sctx + 256;                 // 256
            float* red   = sqh + 256;                  // 9
            const int b = cta & 63;
            const int half = cta >> 6;
            const int koff = half * 256;

            for (int s = tid; s < Ss; s += 256) sattn[s] = g_energy[b * Ss + s];
            sqh[tid] = g_q[(size_t)b * Kk + koff + tid];
            __syncthreads();

            // max
            float m = -3.4e38f;
            for (int s = tid; s < Ss; s += 256) m = fmaxf(m, sattn[s]);
#pragma unroll
            for (int off = 16; off; off >>= 1)
                m = fmaxf(m, __shfl_xor_sync(0xffffffffu, m, off));
            if (lane == 0) red[wid] = m;
            __syncthreads();
            if (wid == 0) {
                float v = (lane < 8) ? red[lane] : -3.4e38f;
#pragma unroll
                for (int off = 4; off; off >>= 1)
                    v = fmaxf(v, __shfl_xor_sync(0xffffffffu, v, off));
                if (lane == 0) red[8] = v;
            }
            __syncthreads();
            const float mx = red[8];
            __syncthreads();

            // exp + sum
            float sum = 0.f;
            for (int s = tid; s < Ss; s += 256) {
                float e = expf(sattn[s] - mx);
                sattn[s] = e;
                sum += e;
            }
#pragma unroll
            for (int off = 16; off; off >>= 1)
                sum += __shfl_xor_sync(0xffffffffu, sum, off);
            if (lane == 0) red[wid] = sum;
            __syncthreads();
            if (wid == 0) {
                float v = (lane < 8) ? red[lane] : 0.f;
#pragma unroll
                for (int off = 4; off; off >>= 1)
                    v += __shfl_xor_sync(0xffffffffu, v, off);
                if (lane == 0) red[8] = v;
            }
            __syncthreads();
            const float inv = 1.f / red[8];
            for (int s = tid; s < Ss; s += 256) sattn[s] *= inv;
            __syncthreads();

            // write attention output (this CTA's half of S)
            for (int s = half * 200 + tid; s < half * 200 + 200; s += 256)
                out_attn[((size_t)b * Tt + t) * Ss + s] = sattn[s];

            // ctx for k in [koff, koff+256)
            {
                const int k = koff + tid;
                const size_t base = (size_t)b * Kk + k;
                const size_t str = (size_t)Bsz * Kk;
                float a0 = 0.f, a1 = 0.f, a2 = 0.f, a3 = 0.f;
                for (int s = 0; s < Ss; s += 4) {
                    a0 += sattn[s]     * values[base + (size_t)s * str];
                    a1 += sattn[s + 1] * values[base + (size_t)(s + 1) * str];
                    a2 += sattn[s + 2] * values[base + (size_t)(s + 2) * str];
                    a3 += sattn[s + 3] * values[base + (size_t)(s + 3) * str];
                }
                float r = (a0 + a1) + (a2 + a3);
                sctx[tid] = r;
                g_ctxb[(size_t)b * Kk + k] = __float2bfloat16_rn(r);
            }
            __syncthreads();

            // partial score over this k-half; combine across halves via atomicAdd
            for (int v = wid; v < Vv; v += 8) {
                const float* wr = w_score + (size_t)v * (2 * Kk);
                float acc = 0.f;
                for (int i = lane; i < 256; i += 32)
                    acc += sqh[i] * wr[koff + i] + sctx[i] * wr[Kk + koff + i];
#pragma unroll
                for (int off = 16; off; off >>= 1)
                    acc += __shfl_xor_sync(0xffffffffu, acc, off);
                if (lane == 0) {
                    float add = acc + (half == 0 ? b_score[v] : 0.f);
                    atomicAdd(&out_pred[((size_t)b * Tt + t) * Vv + v], add);
                }
            }
            __syncthreads();
        }
        grid_bar(ep0 + ++nbar);
    }
}

// ---------------- launch ----------------
extern "C" void kernel_launch(void* const* d_in, const int* in_sizes, int n_in,
                              void* d_out, int out_size) {
    const int*   labels  = (const int*)  d_in[0];
    const float* keys    = (const float*)d_in[1];
    const float* values  = (const float*)d_in[2];
    const float* emb     = (const float*)d_in[3];
    const float* w_ih0   = (const float*)d_in[4];
    const float* w_hh0   = (const float*)d_in[5];
    const float* b_ih0   = (const float*)d_in[6];
    const float* b_hh0   = (const float*)d_in[7];
    const float* w_ih1   = (const float*)d_in[8];
    const float* w_hh1   = (const float*)d_in[9];
    const float* b_ih1   = (const float*)d_in[10];
    const float* b_hh1   = (const float*)d_in[11];
    const float* w_ih2   = (const float*)d_in[12];
    const float* w_hh2   = (const float*)d_in[13];
    const float* b_ih2   = (const float*)d_in[14];
    const float* b_hh2   = (const float*)d_in[15];
    const float* w_proj  = (const float*)d_in[16];
    const float* b_proj  = (const float*)d_in[17];
    const float* w_score = (const float*)d_in[18];
    const float* b_score = (const float*)d_in[19];
    const float* h0      = (const float*)d_in[20];

    float* out_pred = (float*)d_out;
    float* out_attn = out_pred + (size_t)Bsz * Tt * Vv;

    static int configured = 0;
    if (!configured) {
        cudaFuncSetAttribute(decoder_kernel,
                             cudaFuncAttributeMaxDynamicSharedMemorySize, LSTM_SMEM);
        configured = 1;
    }

    decoder_kernel<<<NCTA, 256, LSTM_SMEM>>>(
        labels, keys, values, emb,
        w_ih0, w_hh0, b_ih0, b_hh0,
        w_ih1, w_hh1, b_ih1, b_hh1,
        w_ih2, w_hh2, b_ih2, b_hh2,
        w_proj, b_proj, w_score, b_score, h0,
        out_pred, out_attn);
}

// round 11
// speedup vs baseline: 3.9999x; 1.1019x over previous
#include <cuda_runtime.h>
#include <cuda_bf16.h>
#include <math.h>
#include <stdint.h>
#include <stddef.h>

#define Bsz 64
#define Tt  100
#define Ss  400
#define Ee  512
#define Hh  1024
#define Kk  512
#define Vv  34

#define NCTA 128

typedef __nv_bfloat16 bf16;

// ---------------- static device scratch ----------------
__device__ __align__(256) bf16  g_wcat[3][(size_t)4096 * 2048];  // bf16 weights, concat ih|hh
__device__ __align__(256) bf16  g_xs[(size_t)Tt * Bsz * Ee];     // bf16 embedded inputs
__device__ __align__(256) bf16  g_h1b[2][Bsz * Hh];              // bf16 h states (ping-pong)
__device__ __align__(256) bf16  g_h2b[2][Bsz * Hh];
__device__ __align__(256) bf16  g_h3b[2][Bsz * Hh];
__device__ __align__(256) float g_h3f[2][Bsz * Hh];              // fp32 h3 (for proj)
__device__ __align__(256) float g_c1[Bsz * Hh];
__device__ __align__(256) float g_c2[Bsz * Hh];
__device__ __align__(256) float g_c3[Bsz * Hh];
__device__ __align__(256) bf16  g_ctxb[Bsz * Kk];                // bf16 (gemm input)
__device__ __align__(256) float g_q[Bsz * Kk];
__device__ __align__(256) float g_energy[Bsz * Ss];

// grid barrier state (monotonic epoch; survives replays correctly)
__device__ unsigned g_cnt = 0;
__device__ unsigned g_epoch = 0;

// ---------------- helpers ----------------
__device__ __forceinline__ void cpa16(uint32_t dst, const void* src) {
    asm volatile("cp.async.ca.shared.global [%0], [%1], 16;\n" :: "r"(dst), "l"(src));
}
// evict-first variant: streamed data (weights) should not evict resident K/V
__device__ __forceinline__ void cpa16_ef(uint32_t dst, const void* src, uint64_t pol) {
    asm volatile("cp.async.ca.shared.global.L2::cache_hint [%0], [%1], 16, %2;\n"
                 :: "r"(dst), "l"(src), "l"(pol));
}
#define CPA_COMMIT() asm volatile("cp.async.commit_group;\n" ::: "memory")
#define CPA_WAIT(n)  asm volatile("cp.async.wait_group %0;\n" :: "n"(n) : "memory")

__device__ __forceinline__ void mma_bf16(float* c,
    uint32_t a0, uint32_t a1, uint32_t a2, uint32_t a3,
    uint32_t b0, uint32_t b1) {
    asm volatile(
        "mma.sync.aligned.m16n8k16.row.col.f32.bf16.bf16.f32 "
        "{%0,%1,%2,%3},{%4,%5,%6,%7},{%8,%9},{%0,%1,%2,%3};\n"
        : "+f"(c[0]), "+f"(c[1]), "+f"(c[2]), "+f"(c[3])
        : "r"(a0), "r"(a1), "r"(a2), "r"(a3), "r"(b0), "r"(b1));
}

__device__ __forceinline__ void ldsm4(uint32_t& r0, uint32_t& r1,
                                      uint32_t& r2, uint32_t& r3, uint32_t addr) {
    asm volatile("ldmatrix.sync.aligned.m8n8.x4.shared.b16 {%0,%1,%2,%3}, [%4];"
        : "=r"(r0), "=r"(r1), "=r"(r2), "=r"(r3) : "r"(addr));
}

// grid-wide barrier: release (threadfence) + counting arrive + epoch spin + acquire.
__device__ __forceinline__ void grid_bar(unsigned target) {
    __threadfence();
    __syncthreads();
    if (threadIdx.x == 0) {
        unsigned n = atomicAdd(&g_cnt, 1u);
        if (n == NCTA - 1u) {
            g_cnt = 0;
            __threadfence();
            atomicAdd(&g_epoch, 1u);
        } else {
            while (*(volatile unsigned*)&g_epoch < target) __nanosleep(32);
        }
        __threadfence();       // acquire: invalidates this SM's L1D
    }
    __syncthreads();
}

// ---------------- LSTM tiling constants ----------------
#define BK 64
#define STAGES 7
#define PFD 5
#define APAD 72
#define A_ST (64 * APAD)
#define B_ST (32 * APAD)
#define STAGE_ELE (A_ST + B_ST)
#define LSTM_SMEM (STAGES * STAGE_ELE * 2)

struct SegInfo { const bf16* p; int stride; };

__device__ __forceinline__ SegInfo a_seg(int cell, int p, int t, int seg) {
    SegInfo r;
    if (cell == 0) {
        if (seg == 0)      { r.p = g_xs + (size_t)t * Bsz * Ee; r.stride = Ee; }
        else if (seg == 1) { r.p = g_ctxb;                      r.stride = Kk; }
        else               { r.p = g_h1b[p] + (seg - 2) * 512;  r.stride = Hh; }
    } else if (cell == 1) {
        if (seg < 2) { r.p = g_h1b[1 - p] + seg * 512;       r.stride = Hh; }
        else         { r.p = g_h2b[p]     + (seg - 2) * 512; r.stride = Hh; }
    } else {
        if (seg < 2) { r.p = g_h2b[1 - p] + seg * 512;       r.stride = Hh; }
        else         { r.p = g_h3b[p]     + (seg - 2) * 512; r.stride = Hh; }
    }
    return r;
}

// ---------------- lstm phase (runs on all 128 CTAs) ----------------
__device__ __forceinline__ void lstm_phase(
    char* smem_raw, int cell, int t,
    const float* __restrict__ b_ih, const float* __restrict__ b_hh)
{
    bf16* smem = (bf16*)smem_raw;
    const int p = t & 1;
    const int tid = threadIdx.x;
    const int lane = tid & 31;
    const int warp = tid >> 5;
    const int wm = warp & 3;
    const int wn = warp >> 2;
    const int j0 = blockIdx.x * 8;
    const bf16* __restrict__ wcat = g_wcat[cell];

    uint64_t pol;
    asm("createpolicy.fractional.L2::evict_first.b64 %0;" : "=l"(pol));

    float* c_st; bf16* h_ob; float* h_f;
    if (cell == 0)      { c_st = g_c1; h_ob = g_h1b[1 - p]; h_f = nullptr; }
    else if (cell == 1) { c_st = g_c2; h_ob = g_h2b[1 - p]; h_f = nullptr; }
    else                { c_st = g_c3; h_ob = g_h3b[1 - p]; h_f = g_h3f[1 - p]; }

    const uint32_t smem_u = (uint32_t)__cvta_generic_to_shared(smem);

    float acc0[4] = {0.f, 0.f, 0.f, 0.f};
    float acc1[4] = {0.f, 0.f, 0.f, 0.f};

    const int NTILES = 2048 / BK;

    auto issue_tile = [&](int kt, int ss) {
        const int k0 = kt * BK;
        SegInfo si = a_seg(cell, p, t, k0 >> 9);
        const int kin = k0 & 511;
        const uint32_t abase = smem_u + (uint32_t)(ss * STAGE_ELE) * 2u;
        const uint32_t bbase = abase + (uint32_t)A_ST * 2u;
#pragma unroll
        for (int j = 0; j < 2; j++) {
            int i = tid + j * 256;
            int m = i >> 3, c8 = i & 7;
            const bf16* src = si.p + (size_t)m * si.stride + kin + c8 * 8;
            cpa16(abase + (uint32_t)(m * APAD + c8 * 8) * 2u, src);
        }
        {
            int n = tid >> 3, c8 = tid & 7;
            int r = (n >> 3) * 1024 + j0 + (n & 7);
            const bf16* src = wcat + (size_t)r * 2048 + k0 + c8 * 8;
            cpa16_ef(bbase + (uint32_t)(n * APAD + c8 * 8) * 2u, src, pol);
        }
    };

#pragma unroll
    for (int i = 0; i < PFD; i++) { issue_tile(i, i); CPA_COMMIT(); }

    const uint32_t a_lane_off =
        (uint32_t)((wm * 16 + (lane & 15)) * APAD + (lane >> 4) * 8) * 2u;
    const uint32_t b_lane_off =
        (uint32_t)((wn * 16 + ((lane >> 4) << 3) + (lane & 7)) * APAD
                   + ((lane >> 3) & 1) * 8) * 2u;

    for (int kt = 0; kt < NTILES; kt++) {
        if (kt + PFD < NTILES) issue_tile(kt + PFD, (kt + PFD) % STAGES);
        CPA_COMMIT();
        CPA_WAIT(PFD);
        __syncthreads();

        const uint32_t As_u = smem_u + (uint32_t)((kt % STAGES) * STAGE_ELE) * 2u;
        const uint32_t Bs_u = As_u + (uint32_t)A_ST * 2u;
#pragma unroll
        for (int ks = 0; ks < BK / 16; ks++) {
            const uint32_t kb2 = (uint32_t)(ks * 16) * 2u;
            uint32_t a0, a1, a2, a3, b0, b1, b2, b3;
            ldsm4(a0, a1, a2, a3, As_u + a_lane_off + kb2);
            ldsm4(b0, b1, b2, b3, Bs_u + b_lane_off + kb2);
            mma_bf16(acc0, a0, a1, a2, a3, b0, b1);
            mma_bf16(acc1, a0, a1, a2, a3, b2, b3);
        }
    }
    CPA_WAIT(0);
    __syncthreads();

    float* Cs = (float*)smem_raw;
    {
        const int ar = lane >> 2;
        const int ac = lane & 3;
        int crow = wm * 16 + ar;
        int cc0 = wn * 16 + 2 * ac;
        Cs[crow * 33 + cc0]           = acc0[0];
        Cs[crow * 33 + cc0 + 1]       = acc0[1];
        Cs[(crow + 8) * 33 + cc0]     = acc0[2];
        Cs[(crow + 8) * 33 + cc0 + 1] = acc0[3];
        Cs[crow * 33 + cc0 + 8]       = acc1[0];
        Cs[crow * 33 + cc0 + 9]       = acc1[1];
        Cs[(crow + 8) * 33 + cc0 + 8] = acc1[2];
        Cs[(crow + 8) * 33 + cc0 + 9] = acc1[3];
    }
    __syncthreads();

#pragma unroll
    for (int j = 0; j < 2; j++) {
        int pr = tid + j * 256;
        int m = pr & 63;
        int jj = pr >> 6;
        int jg = j0 + jj;
        float gi = Cs[m * 33 + jj]      + b_ih[jg]        + b_hh[jg];
        float gf = Cs[m * 33 + 8 + jj]  + b_ih[1024 + jg] + b_hh[1024 + jg];
        float gg = Cs[m * 33 + 16 + jj] + b_ih[2048 + jg] + b_hh[2048 + jg];
        float go = Cs[m * 33 + 24 + jj] + b_ih[3072 + jg] + b_hh[3072 + jg];
        float si = 1.f / (1.f + expf(-gi));
        float sf = 1.f / (1.f + expf(-gf));
        float so = 1.f / (1.f + expf(-go));
        float cn = sf * c_st[(size_t)m * Hh + jg] + si * tanhf(gg);
        c_st[(size_t)m * Hh + jg] = cn;
        float hn = so * tanhf(cn);
        h_ob[(size_t)m * Hh + jg] = __float2bfloat16_rn(hn);
        if (h_f) h_f[(size_t)m * Hh + jg] = hn;
    }
}

// ---------------- the single persistent decoder kernel ----------------
__global__ void __launch_bounds__(256, 1) decoder_kernel(
    const int* __restrict__ labels, const float* __restrict__ keys,
    const float* __restrict__ values, const float* __restrict__ emb,
    const float* __restrict__ w_ih0, const float* __restrict__ w_hh0,
    const float* __restrict__ b_ih0, const float* __restrict__ b_hh0,
    const float* __restrict__ w_ih1, const float* __restrict__ w_hh1,
    const float* __restrict__ b_ih1, const float* __restrict__ b_hh1,
    const float* __restrict__ w_ih2, const float* __restrict__ w_hh2,
    const float* __restrict__ b_ih2, const float* __restrict__ b_hh2,
    const float* __restrict__ w_proj, const float* __restrict__ b_proj,
    const float* __restrict__ w_score, const float* __restrict__ b_score,
    const float* __restrict__ h0,
    float* __restrict__ out_pred, float* __restrict__ out_attn)
{
    extern __shared__ __align__(16) char smem_raw[];
    const int tid = threadIdx.x;
    const int cta = blockIdx.x;
    const int lane = tid & 31;
    const int wid = tid >> 5;

    const unsigned ep0 = *(volatile unsigned*)&g_epoch;
    unsigned nbar = 0;

    // ================= PREP =================
    {
        const float* wih[3] = {w_ih0, w_ih1, w_ih2};
        const float* whh[3] = {w_hh0, w_hh1, w_hh2};
        for (int r = cta; r < 3 * 4096; r += NCTA) {
            int cell = r >> 12, row = r & 4095;
            float4 va = ((const float4*)(wih[cell] + (size_t)row * 1024))[tid];
            float4 vb = ((const float4*)(whh[cell] + (size_t)row * 1024))[tid];
            __nv_bfloat162* d2 = (__nv_bfloat162*)(g_wcat[cell] + (size_t)row * 2048);
            d2[2 * tid]           = __floats2bfloat162_rn(va.x, va.y);
            d2[2 * tid + 1]       = __floats2bfloat162_rn(va.z, va.w);
            d2[512 + 2 * tid]     = __floats2bfloat162_rn(vb.x, vb.y);
            d2[512 + 2 * tid + 1] = __floats2bfloat162_rn(vb.z, vb.w);
        }
        // embedding
        for (int tb = cta; tb < Tt * Bsz; tb += NCTA) {
            int t = tb / Bsz, b = tb % Bsz;
            int lab = labels[b * Tt + t];
            if (tid < 128) {
                float4 v = ((const float4*)(emb + (size_t)lab * Ee))[tid];
                __nv_bfloat162* dst =
                    (__nv_bfloat162*)(g_xs + ((size_t)t * Bsz + b) * Ee);
                dst[2 * tid]     = __floats2bfloat162_rn(v.x, v.y);
                dst[2 * tid + 1] = __floats2bfloat162_rn(v.z, v.w);
            }
        }
        // init h/c
#pragma unroll
        for (int j = 0; j < 2; j++) {
            int i = cta * 512 + j * 256 + tid;
            float v = h0[i & (Hh - 1)];
            bf16 vb = __float2bfloat16_rn(v);
            g_h1b[0][i] = vb; g_h2b[0][i] = vb; g_h3b[0][i] = vb;
            g_h3f[0][i] = v;
            g_c1[i] = v; g_c2[i] = v; g_c3[i] = v;
        }
        // zero out_pred (atomicAdd target)
        for (int i = cta * 256 + tid; i < Bsz * Tt * Vv; i += NCTA * 256)
            out_pred[i] = 0.f;
        // ctx0
        float* red = (float*)smem_raw;
        for (int kk = 0; kk < 4; kk++) {
            int k = cta * 4 + kk;
            float s = 0.f;
            for (int i = tid; i < Hh; i += 256)
                s += h0[i] * w_proj[(size_t)k * Hh + i];
#pragma unroll
            for (int off = 16; off; off >>= 1)
                s += __shfl_xor_sync(0xffffffffu, s, off);
            if (lane == 0) red[wid] = s;
            __syncthreads();
            if (tid == 0) {
                float v = 0.f;
#pragma unroll
                for (int j = 0; j < 8; j++) v += red[j];
                red[8] = v + b_proj[k];
            }
            __syncthreads();
            float v = red[8];
            if (tid < Bsz) g_ctxb[(size_t)tid * Kk + k] = __float2bfloat16_rn(v);
            __syncthreads();
        }
    }
    grid_bar(ep0 + ++nbar);

    // ================= TIME LOOP =================
    for (int t = 0; t < Tt; t++) {
        lstm_phase(smem_raw, 0, t, b_ih0, b_hh0);
        grid_bar(ep0 + ++nbar);
        lstm_phase(smem_raw, 1, t, b_ih1, b_hh1);
        grid_bar(ep0 + ++nbar);
        lstm_phase(smem_raw, 2, t, b_ih2, b_hh2);
        grid_bar(ep0 + ++nbar);

        // ---- proj: q = h3 @ w_proj^T + b_proj (kb = cta, 4 k's) ----
        {
            float* sw = (float*)smem_raw;
            const float4* wp4 = (const float4*)(w_proj + (size_t)cta * 4 * 1024);
            float4* sw4 = (float4*)sw;
#pragma unroll
            for (int j = 0; j < 4; j++) sw4[tid + j * 256] = wp4[tid + j * 256];
            __syncthreads();

            const float* h3 = g_h3f[1 - (t & 1)];
            int b = tid >> 2;
            int kl = tid & 3;
            const float4* hr = (const float4*)(h3 + (size_t)b * Hh);
            const float4* w0 = (const float4*)(sw + kl * 1024);
            float a0 = 0.f, a1 = 0.f;
#pragma unroll 4
            for (int i = 0; i < 256; i += 2) {
                float4 h4 = hr[i];
                float4 x0 = w0[i];
                a0 += h4.x * x0.x + h4.y * x0.y + h4.z * x0.z + h4.w * x0.w;
                float4 h5 = hr[i + 1];
                float4 x1 = w0[i + 1];
                a1 += h5.x * x1.x + h5.y * x1.y + h5.z * x1.z + h5.w * x1.w;
            }
            int kg = cta * 4 + kl;
            g_q[(size_t)b * Kk + kg] = a0 + a1 + b_proj[kg];
        }
        grid_bar(ep0 + ++nbar);

        // ---- energy: cta -> (b = cta&63, half = cta>>6), 200 s each ----
        {
            float* sq = (float*)smem_raw;
            const int b = cta & 63;
            const int half = cta >> 6;
            if (tid < 128)
                ((float4*)sq)[tid] = ((const float4*)(g_q + (size_t)b * Kk))[tid];
            __syncthreads();
            const float4* qr = (const float4*)sq;
            const int base = half * 200;
            // 2 s-rows in flight per warp (MLP x2); 12 paired iters + 1 tail
#pragma unroll 2
            for (int i = 0; i < 12; i++) {
                int s1 = base + wid + 16 * i;
                int s2 = s1 + 8;
                const float4* k1 = (const float4*)(keys + ((size_t)s1 * Bsz + b) * Kk);
                const float4* k2 = (const float4*)(keys + ((size_t)s2 * Bsz + b) * Kk);
                float acc1 = 0.f, acc2 = 0.f;
#pragma unroll
                for (int u = 0; u < 4; u++) {
                    float4 q4 = qr[lane + u * 32];
                    float4 a4 = k1[lane + u * 32];
                    float4 b4 = k2[lane + u * 32];
                    acc1 += a4.x * q4.x + a4.y * q4.y + a4.z * q4.z + a4.w * q4.w;
                    acc2 += b4.x * q4.x + b4.y * q4.y + b4.z * q4.z + b4.w * q4.w;
                }
#pragma unroll
                for (int off = 16; off; off >>= 1) {
                    acc1 += __shfl_xor_sync(0xffffffffu, acc1, off);
                    acc2 += __shfl_xor_sync(0xffffffffu, acc2, off);
                }
                if (lane == 0) {
                    g_energy[b * Ss + s1] = acc1;
                    g_energy[b * Ss + s2] = acc2;
                }
            }
            {   // tail: s = base + 192 + wid
                int s = base + 192 + wid;
                const float4* kr = (const float4*)(keys + ((size_t)s * Bsz + b) * Kk);
                float acc = 0.f;
#pragma unroll
                for (int u = 0; u < 4; u++) {
                    float4 k4 = kr[lane + u * 32];
                    float4 q4 = qr[lane + u * 32];
                    acc += k4.x * q4.x + k4.y * q4.y + k4.z * q4.z + k4.w * q4.w;
                }
#pragma unroll
                for (int off = 16; off; off >>= 1)
                    acc += __shfl_xor_sync(0xffffffffu, acc, off);
                if (lane == 0) g_energy[b * Ss + s] = acc;
            }
            __syncthreads();
        }
        grid_bar(ep0 + ++nbar);

        // ---- softmax + ctx + partial score (cta -> b, half k-range) ----
        {
            float* sattn = (float*)smem_raw;          // 400
            float* sctx  = sattn + Ss;                 // 256
            float* sqh   = sctx + 256;                 // 256
            float* red   = sqh + 256;                  // 9
            const int b = cta & 63;
            const int half = cta >> 6;
            const int koff = half * 256;

            for (int s = tid; s < Ss; s += 256) sattn[s] = g_energy[b * Ss + s];
            sqh[tid] = g_q[(size_t)b * Kk + koff + tid];
            __syncthreads();

            // max
            float m = -3.4e38f;
            for (int s = tid; s < Ss; s += 256) m = fmaxf(m, sattn[s]);
#pragma unroll
            for (int off = 16; off; off >>= 1)
                m = fmaxf(m, __shfl_xor_sync(0xffffffffu, m, off));
            if (lane == 0) red[wid] = m;
            __syncthreads();
            if (wid == 0) {
                float v = (lane < 8) ? red[lane] : -3.4e38f;
#pragma unroll
                for (int off = 4; off; off >>= 1)
                    v = fmaxf(v, __shfl_xor_sync(0xffffffffu, v, off));
                if (lane == 0) red[8] = v;
            }
            __syncthreads();
            const float mx = red[8];
            __syncthreads();

            // exp + sum
            float sum = 0.f;
            for (int s = tid; s < Ss; s += 256) {
                float e = expf(sattn[s] - mx);
                sattn[s] = e;
                sum += e;
            }
#pragma unroll
            for (int off = 16; off; off >>= 1)
                sum += __shfl_xor_sync(0xffffffffu, sum, off);
            if (lane == 0) red[wid] = sum;
            __syncthreads();
            if (wid == 0) {
                float v = (lane < 8) ? red[lane] : 0.f;
#pragma unroll
                for (int off = 4; off; off >>= 1)
                    v += __shfl_xor_sync(0xffffffffu, v, off);
                if (lane == 0) red[8] = v;
            }
            __syncthreads();
            const float inv = 1.f / red[8];
            for (int s = tid; s < Ss; s += 256) sattn[s] *= inv;
            __syncthreads();

            // write attention output (this CTA's half of S)
            for (int s = half * 200 + tid; s < half * 200 + 200; s += 256)
                out_attn[((size_t)b * Tt + t) * Ss + s] = sattn[s];

            // ctx for k in [koff, koff+256), fp32 values
            {
                const int k = koff + tid;
                const size_t base = (size_t)b * Kk + k;
                const size_t str = (size_t)Bsz * Kk;
                float a0 = 0.f, a1 = 0.f, a2 = 0.f, a3 = 0.f;
                for (int s = 0; s < Ss; s += 4) {
                    a0 += sattn[s]     * values[base + (size_t)s * str];
                    a1 += sattn[s + 1] * values[base + (size_t)(s + 1) * str];
                    a2 += sattn[s + 2] * values[base + (size_t)(s + 2) * str];
                    a3 += sattn[s + 3] * values[base + (size_t)(s + 3) * str];
                }
                float r = (a0 + a1) + (a2 + a3);
                sctx[tid] = r;
                g_ctxb[(size_t)b * Kk + k] = __float2bfloat16_rn(r);
            }
            __syncthreads();

            // partial score over this k-half; combine across halves via atomicAdd
            for (int v = wid; v < Vv; v += 8) {
                const float* wr = w_score + (size_t)v * (2 * Kk);
                float acc = 0.f;
                for (int i = lane; i < 256; i += 32)
                    acc += sqh[i] * wr[koff + i] + sctx[i] * wr[Kk + koff + i];
#pragma unroll
                for (int off = 16; off; off >>= 1)
                    acc += __shfl_xor_sync(0xffffffffu, acc, off);
                if (lane == 0) {
                    float add = acc + (half == 0 ? b_score[v] : 0.f);
                    atomicAdd(&out_pred[((size_t)b * Tt + t) * Vv + v], add);
                }
            }
            __syncthreads();
        }
        grid_bar(ep0 + ++nbar);
    }
}

// ---------------- launch ----------------
extern "C" void kernel_launch(void* const* d_in, const int* in_sizes, int n_in,
                              void* d_out, int out_size) {
    const int*   labels  = (const int*)  d_in[0];
    const float* keys    = (const float*)d_in[1];
    const float* values  = (const float*)d_in[2];
    const float* emb     = (const float*)d_in[3];
    const float* w_ih0   = (const float*)d_in[4];
    const float* w_hh0   = (const float*)d_in[5];
    const float* b_ih0   = (const float*)d_in[6];
    const float* b_hh0   = (const float*)d_in[7];
    const float* w_ih1   = (const float*)d_in[8];
    const float* w_hh1   = (const float*)d_in[9];
    const float* b_ih1   = (const float*)d_in[10];
    const float* b_hh1   = (const float*)d_in[11];
    const float* w_ih2   = (const float*)d_in[12];
    const float* w_hh2   = (const float*)d_in[13];
    const float* b_ih2   = (const float*)d_in[14];
    const float* b_hh2   = (const float*)d_in[15];
    const float* w_proj  = (const float*)d_in[16];
    const float* b_proj  = (const float*)d_in[17];
    const float* w_score = (const float*)d_in[18];
    const float* b_score = (const float*)d_in[19];
    const float* h0      = (const float*)d_in[20];

    float* out_pred = (float*)d_out;
    float* out_attn = out_pred + (size_t)Bsz * Tt * Vv;

    static int configured = 0;
    if (!configured) {
        cudaFuncSetAttribute(decoder_kernel,
                             cudaFuncAttributeMaxDynamicSharedMemorySize, LSTM_SMEM);
        configured = 1;
    }

    decoder_kernel<<<NCTA, 256, LSTM_SMEM>>>(
        labels, keys, values, emb,
        w_ih0, w_hh0, b_ih0, b_hh0,
        w_ih1, w_hh1, b_ih1, b_hh1,
        w_ih2, w_hh2, b_ih2, b_hh2,
        w_proj, b_proj, w_score, b_score, h0,
        out_pred, out_attn);
}